// round 1
// baseline (speedup 1.0000x reference)
#include <cuda_runtime.h>
#include <math.h>

#define NN 32
#define DD 512
#define PP 3136
#define KK 64
#define PSPLIT 4
#define PCHUNK 784   // PP / PSPLIT

// Scratch (static device globals — no allocation)
__device__ float g_rnorm[NN * PP];                       // 401 KB
__device__ float g_wT[DD * KK];                          // 128 KB
__device__ float g_soft[(size_t)NN * KK * PP];           // 25.7 MB
__device__ float g_aggp[(size_t)PSPLIT * NN * KK * DD];  // 16 MB

// ---------------------------------------------------------------------------
// 1) inverse L2 norm per pixel: g_rnorm[n,p] = 1 / max(||x[n,:,p]||, 1e-12)
// ---------------------------------------------------------------------------
__global__ void __launch_bounds__(256) k_rnorm(const float* __restrict__ x) {
    int idx = blockIdx.x * 256 + threadIdx.x;
    if (idx >= NN * PP) return;
    int n = idx / PP, p = idx - n * PP;
    const float* xp = x + (size_t)n * DD * PP + p;
    float s = 0.f;
#pragma unroll 8
    for (int d = 0; d < DD; ++d) {
        float v = xp[(size_t)d * PP];
        s = fmaf(v, v, s);
    }
    g_rnorm[idx] = 1.f / fmaxf(sqrtf(s), 1e-12f);
}

// ---------------------------------------------------------------------------
// 2) transpose conv_w (K,D) -> (D,K) for coalesced/vectorized shared loads
// ---------------------------------------------------------------------------
__global__ void __launch_bounds__(256) k_wT(const float* __restrict__ w) {
    int idx = blockIdx.x * 256 + threadIdx.x;
    if (idx >= KK * DD) return;
    int k = idx / DD, d = idx - k * DD;
    g_wT[d * KK + k] = w[idx];
}

// ---------------------------------------------------------------------------
// 3) logits GEMM + softmax over K, fused. One block = (n, 128-pixel tile).
//    Tile: K=64 x P=128, 8x8 register blocking, DC=16 d-chunks.
// ---------------------------------------------------------------------------
__global__ void __launch_bounds__(128) k_logits_softmax(const float* __restrict__ x) {
    const int n  = blockIdx.y;
    const int p0 = blockIdx.x * 128;
    const int tid = threadIdx.x;
    __shared__ float sm[8320];   // union: mainloop ws[16][68]+xs[16][132], epilogue lg[64][130]
    __shared__ float rn[128];
    float* ws = sm;              // 1088 floats
    float* xs = sm + 1088;       // 2112 floats

    {
        int p = p0 + tid;
        rn[tid] = (p < PP) ? g_rnorm[n * PP + p] : 0.f;
    }
    __syncthreads();

    float acc[8][8];
#pragma unroll
    for (int i = 0; i < 8; ++i)
#pragma unroll
        for (int j = 0; j < 8; ++j) acc[i][j] = 0.f;

    const int tk = tid >> 4;   // 0..7  -> k group of 8
    const int tp = tid & 15;   // 0..15 -> p group of 8
    const float* xn = x + (size_t)n * DD * PP;

    for (int d0 = 0; d0 < DD; d0 += 16) {
#pragma unroll
        for (int i = 0; i < 8; ++i) {
            int e = i * 128 + tid;
            int dl = e >> 6, k = e & 63;
            ws[dl * 68 + k] = g_wT[(d0 + dl) * KK + k];
        }
#pragma unroll
        for (int i = 0; i < 16; ++i) {
            int e = i * 128 + tid;
            int dl = e >> 7, pl = e & 127;
            int p = p0 + pl;
            float v = (p < PP) ? xn[(size_t)(d0 + dl) * PP + p] : 0.f;
            xs[dl * 132 + pl] = v * rn[pl];
        }
        __syncthreads();
#pragma unroll
        for (int dl = 0; dl < 16; ++dl) {
            float4 wa = *(const float4*)&ws[dl * 68 + tk * 8];
            float4 wb = *(const float4*)&ws[dl * 68 + tk * 8 + 4];
            float4 xa = *(const float4*)&xs[dl * 132 + tp * 8];
            float4 xb = *(const float4*)&xs[dl * 132 + tp * 8 + 4];
            float wr[8] = {wa.x, wa.y, wa.z, wa.w, wb.x, wb.y, wb.z, wb.w};
            float xr[8] = {xa.x, xa.y, xa.z, xa.w, xb.x, xb.y, xb.z, xb.w};
#pragma unroll
            for (int i = 0; i < 8; ++i)
#pragma unroll
                for (int j = 0; j < 8; ++j)
                    acc[i][j] = fmaf(wr[i], xr[j], acc[i][j]);
        }
        __syncthreads();
    }

    // stage logits into shared [64][130]
#pragma unroll
    for (int i = 0; i < 8; ++i)
#pragma unroll
        for (int j = 0; j < 8; ++j)
            sm[(tk * 8 + i) * 130 + tp * 8 + j] = acc[i][j];
    __syncthreads();

    // softmax over K per pixel; thread <-> pixel
    int p = p0 + tid;
    if (p < PP) {
        float m = -1e30f;
#pragma unroll
        for (int k = 0; k < KK; ++k) m = fmaxf(m, sm[k * 130 + tid]);
        float ssum = 0.f;
#pragma unroll
        for (int k = 0; k < KK; ++k) ssum += expf(sm[k * 130 + tid] - m);
        float inv = 1.f / ssum;
        float* outp = g_soft + (size_t)n * KK * PP + p;
#pragma unroll
        for (int k = 0; k < KK; ++k)
            outp[(size_t)k * PP] = expf(sm[k * 130 + tid] - m) * inv;
    }
}

// ---------------------------------------------------------------------------
// 4) agg GEMM: aggp[ps,n,k,d] = sum_{p in chunk ps} a[n,k,p] * x[n,d,p]*rn[n,p]
//    Block = (d-tile of 64, n, p-split). Tile K=64 x D=64, 8x4 per thread.
// ---------------------------------------------------------------------------
__global__ void __launch_bounds__(128) k_agg(const float* __restrict__ x) {
    const int d0 = blockIdx.x * 64;
    const int n  = blockIdx.y;
    const int ps = blockIdx.z;
    const int tid = threadIdx.x;
    const int tk = tid >> 4;   // 0..7  -> k group of 8
    const int td = tid & 15;   // 0..15 -> d group of 4
    __shared__ float as_[KK * 33];   // [k][pc]
    __shared__ float xs_[64 * 33];   // [d][pc]

    float acc[8][4];
#pragma unroll
    for (int i = 0; i < 8; ++i)
#pragma unroll
        for (int j = 0; j < 4; ++j) acc[i][j] = 0.f;

    const float* xn  = x + (size_t)n * DD * PP;
    const float* an  = g_soft + (size_t)n * KK * PP;
    const float* rnb = g_rnorm + n * PP;
    const int pbeg = ps * PCHUNK;
    const int pend = pbeg + PCHUNK;

    for (int pc0 = pbeg; pc0 < pend; pc0 += 32) {
        int valid = pend - pc0;
        if (valid > 32) valid = 32;
        __syncthreads();
#pragma unroll
        for (int i = 0; i < 16; ++i) {
            int e = i * 128 + tid;
            int k = e >> 5, pl = e & 31;
            as_[k * 33 + pl] = (pl < valid) ? an[(size_t)k * PP + pc0 + pl] : 0.f;
        }
#pragma unroll
        for (int i = 0; i < 16; ++i) {
            int e = i * 128 + tid;
            int d = e >> 5, pl = e & 31;
            xs_[d * 33 + pl] = (pl < valid)
                ? xn[(size_t)(d0 + d) * PP + pc0 + pl] * rnb[pc0 + pl]
                : 0.f;
        }
        __syncthreads();
#pragma unroll 8
        for (int pc = 0; pc < 32; ++pc) {
            float xr[4];
#pragma unroll
            for (int j = 0; j < 4; ++j) xr[j] = xs_[(td * 4 + j) * 33 + pc];
#pragma unroll
            for (int i = 0; i < 8; ++i) {
                float a = as_[(tk * 8 + i) * 33 + pc];
#pragma unroll
                for (int j = 0; j < 4; ++j)
                    acc[i][j] = fmaf(a, xr[j], acc[i][j]);
            }
        }
    }

    float* outp = g_aggp + ((size_t)(ps * NN + n) * KK) * DD;
#pragma unroll
    for (int i = 0; i < 8; ++i)
#pragma unroll
        for (int j = 0; j < 4; ++j)
            outp[(size_t)(tk * 8 + i) * DD + d0 + td * 4 + j] = acc[i][j];
}

// ---------------------------------------------------------------------------
// 5) vlad: a_sum reduction + (agg - a_sum*c) + intra L2 norm. Block = (k, n).
// ---------------------------------------------------------------------------
__global__ void __launch_bounds__(128) k_vlad(const float* __restrict__ centroids,
                                              float* __restrict__ out) {
    const int k = blockIdx.x;
    const int n = blockIdx.y;
    const int tid = threadIdx.x;
    __shared__ float red[128];

    // phase 1: a_sum over P
    const float* ap = g_soft + ((size_t)n * KK + k) * PP;
    float s = 0.f;
    for (int i = tid; i < PP; i += 128) s += ap[i];
    red[tid] = s;
    __syncthreads();
    for (int w = 64; w > 0; w >>= 1) {
        if (tid < w) red[tid] += red[tid + w];
        __syncthreads();
    }
    float asum = red[0];
    __syncthreads();

    // phase 2: vlad + intra norm
    float v[4];
    float ss = 0.f;
#pragma unroll
    for (int j = 0; j < 4; ++j) {
        int d = j * 128 + tid;
        float a = 0.f;
#pragma unroll
        for (int ps = 0; ps < PSPLIT; ++ps)
            a += g_aggp[(((size_t)ps * NN + n) * KK + k) * DD + d];
        v[j] = a - asum * centroids[k * DD + d];
        ss = fmaf(v[j], v[j], ss);
    }
    red[tid] = ss;
    __syncthreads();
    for (int w = 64; w > 0; w >>= 1) {
        if (tid < w) red[tid] += red[tid + w];
        __syncthreads();
    }
    float rinv = 1.f / fmaxf(sqrtf(red[0]), 1e-12f);
    const size_t base = ((size_t)n * KK + k) * DD;
#pragma unroll
    for (int j = 0; j < 4; ++j)
        out[base + j * 128 + tid] = v[j] * rinv;
}

// ---------------------------------------------------------------------------
// 6) global L2 norm per n over K*D
// ---------------------------------------------------------------------------
__global__ void __launch_bounds__(256) k_gnorm(float* __restrict__ out) {
    const int n = blockIdx.x;
    const int tid = threadIdx.x;
    __shared__ float red[256];
    float* row = out + (size_t)n * KK * DD;
    float ss = 0.f;
    for (int i = tid; i < KK * DD; i += 256) {
        float v = row[i];
        ss = fmaf(v, v, ss);
    }
    red[tid] = ss;
    __syncthreads();
    for (int w = 128; w > 0; w >>= 1) {
        if (tid < w) red[tid] += red[tid + w];
        __syncthreads();
    }
    float rinv = 1.f / fmaxf(sqrtf(red[0]), 1e-12f);
    for (int i = tid; i < KK * DD; i += 256) row[i] *= rinv;
}

// ---------------------------------------------------------------------------
extern "C" void kernel_launch(void* const* d_in, const int* in_sizes, int n_in,
                              void* d_out, int out_size) {
    const float* x = (const float*)d_in[0];        // (32, 512, 56, 56)
    const float* w = (const float*)d_in[1];        // (64, 512)
    const float* c = (const float*)d_in[2];        // (64, 512)
    float* out = (float*)d_out;                    // (32, 32768) fp32

    k_rnorm<<<(NN * PP + 255) / 256, 256>>>(x);
    k_wT<<<(KK * DD + 255) / 256, 256>>>(w);

    dim3 gB((PP + 127) / 128, NN);                 // 25 x 32
    k_logits_softmax<<<gB, 128>>>(x);

    dim3 gC(DD / 64, NN, PSPLIT);                  // 8 x 32 x 4
    k_agg<<<gC, 128>>>(x);

    dim3 gD(KK, NN);                               // 64 x 32
    k_vlad<<<gD, 128>>>(c, out);

    k_gnorm<<<NN, 256>>>(out);
}

// round 4
// speedup vs baseline: 1.5357x; 1.5357x over previous
#include <cuda_runtime.h>
#include <math.h>

#define NN 32
#define DD 512
#define PP 3136
#define KK 64
#define PSPLIT 4
#define PCHUNK 784   // PP / PSPLIT
#define NTILE 25     // ceil(PP/128) pixel tiles per image

// Scratch (static device globals — no allocation)
__device__ float g_rnorm[NN * PP];                        // 401 KB
__device__ float g_wT[DD * KK];                           // 128 KB
__device__ float g_soft[(size_t)NN * KK * PP];            // holds a*rn  (25.7 MB)
__device__ float g_aggp[(size_t)PSPLIT * NN * KK * DD];   // 16 MB
__device__ float g_asumt[NN * KK * NTILE];                // 200 KB (per-tile a sums)

// ---------------------------------------------------------------------------
// 1) inverse L2 norm per pixel (float4 over p: 4 pixels / thread)
// ---------------------------------------------------------------------------
__global__ void __launch_bounds__(128) k_rnorm(const float* __restrict__ x) {
    const int Q = PP / 4;   // 784 float4 per (n,d) row
    int idx = blockIdx.x * 128 + threadIdx.x;
    if (idx >= NN * Q) return;
    int n = idx / Q, q = idx - n * Q;
    const float* base = x + (size_t)n * DD * PP + q * 4;
    float s0 = 0.f, s1 = 0.f, s2 = 0.f, s3 = 0.f;
#pragma unroll 8
    for (int d = 0; d < DD; ++d) {
        float4 v = *(const float4*)(base + (size_t)d * PP);
        s0 = fmaf(v.x, v.x, s0);
        s1 = fmaf(v.y, v.y, s1);
        s2 = fmaf(v.z, v.z, s2);
        s3 = fmaf(v.w, v.w, s3);
    }
    float4 r;
    r.x = 1.f / fmaxf(sqrtf(s0), 1e-12f);
    r.y = 1.f / fmaxf(sqrtf(s1), 1e-12f);
    r.z = 1.f / fmaxf(sqrtf(s2), 1e-12f);
    r.w = 1.f / fmaxf(sqrtf(s3), 1e-12f);
    *(float4*)(g_rnorm + (size_t)n * PP + q * 4) = r;
}

// ---------------------------------------------------------------------------
// 2) transpose conv_w (K,D) -> (D,K)
// ---------------------------------------------------------------------------
__global__ void __launch_bounds__(256) k_wT(const float* __restrict__ w) {
    int idx = blockIdx.x * 256 + threadIdx.x;
    if (idx >= KK * DD) return;
    int k = idx / DD, d = idx - k * DD;
    g_wT[d * KK + k] = w[idx];
}

// ---------------------------------------------------------------------------
// 3) logits GEMM + softmax over K, fused. Block = (n, 128-pixel tile).
//    Stores a*rn[p] into g_soft and per-tile sum_p a into g_asumt.
// ---------------------------------------------------------------------------
__global__ void __launch_bounds__(128) k_logits_softmax(const float* __restrict__ x) {
    const int n  = blockIdx.y;
    const int bx = blockIdx.x;
    const int p0 = bx * 128;
    const int tid = threadIdx.x;
    __shared__ float sm[64 * 129];   // union: mainloop ws(16x68)+xs(16x132); epi: logits/a [64][129]
    __shared__ float rn[128];
    __shared__ float red[128];
    float* ws = sm;                  // 16*68  = 1088 floats
    float* xs = sm + 1088;           // 16*132 = 2112 floats

    const int valid = (PP - p0 < 128) ? (PP - p0) : 128;   // 128 or 64

    {
        int p = p0 + tid;
        rn[tid] = (tid < valid) ? g_rnorm[n * PP + p] : 0.f;
    }
    __syncthreads();

    float acc[8][8];
#pragma unroll
    for (int i = 0; i < 8; ++i)
#pragma unroll
        for (int j = 0; j < 8; ++j) acc[i][j] = 0.f;

    const int tk = tid >> 4;   // 0..7
    const int tp = tid & 15;   // 0..15
    const float* xn = x + (size_t)n * DD * PP;

    for (int d0 = 0; d0 < DD; d0 += 16) {
        // ws: 16 d x 64 k  -> 2 float4 per thread
#pragma unroll
        for (int t = 0; t < 2; ++t) {
            int e = t * 128 + tid;           // 0..255
            int dl = e >> 4, grp = e & 15;   // grp = group of 4 k
            float4 v = *(const float4*)(g_wT + (d0 + dl) * KK + grp * 4);
            *(float4*)&ws[dl * 68 + grp * 4] = v;
        }
        // xs: 16 d x 128 p -> 4 float4 per thread, scaled by rn
#pragma unroll
        for (int t = 0; t < 4; ++t) {
            int e = t * 128 + tid;           // 0..511
            int dl = e >> 3, grp = e & 7;    // grp = group of 16 p? no: 8 groups of 4? need 32 grp
            // 16 d rows x 32 float4-groups = 512 tasks
            dl = e >> 5; grp = e & 31;
            float4 v = make_float4(0.f, 0.f, 0.f, 0.f);
            if (grp * 4 < valid)
                v = *(const float4*)(xn + (size_t)(d0 + dl) * PP + p0 + grp * 4);
            v.x *= rn[grp * 4 + 0];
            v.y *= rn[grp * 4 + 1];
            v.z *= rn[grp * 4 + 2];
            v.w *= rn[grp * 4 + 3];
            *(float4*)&xs[dl * 132 + grp * 4] = v;
        }
        __syncthreads();
#pragma unroll
        for (int dl = 0; dl < 16; ++dl) {
            float4 wa = *(const float4*)&ws[dl * 68 + tk * 8];
            float4 wb = *(const float4*)&ws[dl * 68 + tk * 8 + 4];
            float4 xa = *(const float4*)&xs[dl * 132 + tp * 4];        // p = tp*4 + {0..3}
            float4 xb = *(const float4*)&xs[dl * 132 + 64 + tp * 4];   // p = 64 + tp*4 + {0..3}
            float wr[8] = {wa.x, wa.y, wa.z, wa.w, wb.x, wb.y, wb.z, wb.w};
            float xr[8] = {xa.x, xa.y, xa.z, xa.w, xb.x, xb.y, xb.z, xb.w};
#pragma unroll
            for (int i = 0; i < 8; ++i)
#pragma unroll
                for (int j = 0; j < 8; ++j)
                    acc[i][j] = fmaf(wr[i], xr[j], acc[i][j]);
        }
        __syncthreads();
    }

    // stage logits into sm[64][129]; pixel mapping matches xr
#pragma unroll
    for (int i = 0; i < 8; ++i) {
        int k = tk * 8 + i;
#pragma unroll
        for (int j = 0; j < 8; ++j) {
            int pl = (j < 4) ? (tp * 4 + j) : (64 + tp * 4 + (j - 4));
            sm[k * 129 + pl] = acc[i][j];
        }
    }
    __syncthreads();

    // softmax over K; thread <-> pixel
    const bool pv = (tid < valid);
    float m = -1e30f;
#pragma unroll
    for (int k = 0; k < KK; ++k) m = fmaxf(m, sm[k * 129 + tid]);
    float ssum = 0.f;
#pragma unroll
    for (int k = 0; k < KK; ++k) ssum += __expf(sm[k * 129 + tid] - m);
    float inv = 1.f / ssum;
    float rnv = rn[tid];
    float* outp = g_soft + (size_t)n * KK * PP + p0 + tid;
#pragma unroll
    for (int k = 0; k < KK; ++k) {
        float a = pv ? __expf(sm[k * 129 + tid] - m) * inv : 0.f;
        sm[k * 129 + tid] = a;                       // unscaled a for reduction
        if (pv) outp[(size_t)k * PP] = a * rnv;      // scaled a for agg GEMM
    }
    __syncthreads();

    // per-tile a_sum: reduce sm rows over 128 pixels
    {
        int kk = tid >> 1, h = tid & 1;
        float s = 0.f;
#pragma unroll 16
        for (int j = 0; j < 64; ++j) s += sm[kk * 129 + h * 64 + j];
        red[tid] = s;
    }
    __syncthreads();
    if (tid < KK)
        g_asumt[(n * KK + tid) * NTILE + bx] = red[2 * tid] + red[2 * tid + 1];
}

// ---------------------------------------------------------------------------
// 4) agg GEMM: aggp[ps,n,k,d] = sum_{p in chunk} (a*rn)[n,k,p] * x[n,d,p]
//    Block = (d-tile 128, n, p-split). Tile K=64 x D=128, 8x8 per thread,
//    stride-interleaved thread maps (conflict-free pitch-33 smem).
// ---------------------------------------------------------------------------
__global__ void __launch_bounds__(128) k_agg(const float* __restrict__ x) {
    const int d0 = blockIdx.x * 128;
    const int n  = blockIdx.y;
    const int ps = blockIdx.z;
    const int tid = threadIdx.x;
    const int tk = tid >> 4;   // 0..7
    const int td = tid & 15;   // 0..15
    __shared__ float as_[KK * 33];    // [k][pc] pitch 33
    __shared__ float xs_[128 * 33];   // [d][pc] pitch 33

    float acc[8][8];
#pragma unroll
    for (int i = 0; i < 8; ++i)
#pragma unroll
        for (int j = 0; j < 8; ++j) acc[i][j] = 0.f;

    const float* xn = x + (size_t)n * DD * PP;
    const float* an = g_soft + (size_t)n * KK * PP;
    const int pbeg = ps * PCHUNK;
    const int pend = pbeg + PCHUNK;

    for (int pc0 = pbeg; pc0 < pend; pc0 += 32) {
        int valid = pend - pc0;
        if (valid > 32) valid = 32;   // 32 or 16 (784 = 24*32+16)
        __syncthreads();
        // a tile: 64 k x 32 pc -> 4 float4 per thread
#pragma unroll
        for (int t = 0; t < 4; ++t) {
            int e = t * 128 + tid;          // 0..511
            int row = e >> 3, grp = e & 7;
            float4 v = make_float4(0.f, 0.f, 0.f, 0.f);
            if (grp * 4 < valid)
                v = *(const float4*)(an + (size_t)row * PP + pc0 + grp * 4);
            as_[row * 33 + grp * 4 + 0] = v.x;
            as_[row * 33 + grp * 4 + 1] = v.y;
            as_[row * 33 + grp * 4 + 2] = v.z;
            as_[row * 33 + grp * 4 + 3] = v.w;
        }
        // x tile: 128 d x 32 pc -> 8 float4 per thread
#pragma unroll
        for (int t = 0; t < 8; ++t) {
            int e = t * 128 + tid;          // 0..1023
            int row = e >> 3, grp = e & 7;
            float4 v = make_float4(0.f, 0.f, 0.f, 0.f);
            if (grp * 4 < valid)
                v = *(const float4*)(xn + (size_t)(d0 + row) * PP + pc0 + grp * 4);
            xs_[row * 33 + grp * 4 + 0] = v.x;
            xs_[row * 33 + grp * 4 + 1] = v.y;
            xs_[row * 33 + grp * 4 + 2] = v.z;
            xs_[row * 33 + grp * 4 + 3] = v.w;
        }
        __syncthreads();
#pragma unroll 4
        for (int pc = 0; pc < 32; ++pc) {
            float ar[8], xr[8];
#pragma unroll
            for (int i = 0; i < 8; ++i) ar[i] = as_[(i * 8 + tk) * 33 + pc];
#pragma unroll
            for (int j = 0; j < 8; ++j) xr[j] = xs_[(j * 16 + td) * 33 + pc];
#pragma unroll
            for (int i = 0; i < 8; ++i)
#pragma unroll
                for (int j = 0; j < 8; ++j)
                    acc[i][j] = fmaf(ar[i], xr[j], acc[i][j]);
        }
    }

    float* outp = g_aggp + ((size_t)(ps * NN + n) * KK) * DD + d0;
#pragma unroll
    for (int i = 0; i < 8; ++i) {
        int k = i * 8 + tk;
#pragma unroll
        for (int j = 0; j < 8; ++j)
            outp[(size_t)k * DD + j * 16 + td] = acc[i][j];
    }
}

// ---------------------------------------------------------------------------
// 5) vlad: a_sum (from tile partials) + (agg - a_sum*c) + intra L2 norm
// ---------------------------------------------------------------------------
__global__ void __launch_bounds__(128) k_vlad(const float* __restrict__ centroids,
                                              float* __restrict__ out) {
    const int k = blockIdx.x;
    const int n = blockIdx.y;
    const int tid = threadIdx.x;
    __shared__ float red[128];

    float asum = 0.f;
    const float* at = g_asumt + (n * KK + k) * NTILE;
#pragma unroll
    for (int t = 0; t < NTILE; ++t) asum += at[t];

    float v[4];
    float ss = 0.f;
#pragma unroll
    for (int j = 0; j < 4; ++j) {
        int d = j * 128 + tid;
        float a = 0.f;
#pragma unroll
        for (int ps = 0; ps < PSPLIT; ++ps)
            a += g_aggp[(((size_t)ps * NN + n) * KK + k) * DD + d];
        v[j] = a - asum * centroids[k * DD + d];
        ss = fmaf(v[j], v[j], ss);
    }
    red[tid] = ss;
    __syncthreads();
    for (int w = 64; w > 0; w >>= 1) {
        if (tid < w) red[tid] += red[tid + w];
        __syncthreads();
    }
    float rinv = 1.f / fmaxf(sqrtf(red[0]), 1e-12f);
    const size_t base = ((size_t)n * KK + k) * DD;
#pragma unroll
    for (int j = 0; j < 4; ++j)
        out[base + j * 128 + tid] = v[j] * rinv;
}

// ---------------------------------------------------------------------------
// 6) global L2 norm per n over K*D
// ---------------------------------------------------------------------------
__global__ void __launch_bounds__(256) k_gnorm(float* __restrict__ out) {
    const int n = blockIdx.x;
    const int tid = threadIdx.x;
    __shared__ float red[256];
    float* row = out + (size_t)n * KK * DD;
    float ss = 0.f;
    for (int i = tid; i < KK * DD; i += 256) {
        float v = row[i];
        ss = fmaf(v, v, ss);
    }
    red[tid] = ss;
    __syncthreads();
    for (int w = 128; w > 0; w >>= 1) {
        if (tid < w) red[tid] += red[tid + w];
        __syncthreads();
    }
    float rinv = 1.f / fmaxf(sqrtf(red[0]), 1e-12f);
    for (int i = tid; i < KK * DD; i += 256) row[i] *= rinv;
}

// ---------------------------------------------------------------------------
extern "C" void kernel_launch(void* const* d_in, const int* in_sizes, int n_in,
                              void* d_out, int out_size) {
    const float* x = (const float*)d_in[0];        // (32, 512, 56, 56)
    const float* w = (const float*)d_in[1];        // (64, 512)
    const float* c = (const float*)d_in[2];        // (64, 512)
    float* out = (float*)d_out;                    // (32, 32768) fp32

    k_rnorm<<<(NN * (PP / 4) + 127) / 128, 128>>>(x);
    k_wT<<<(KK * DD + 255) / 256, 256>>>(w);

    dim3 gB(NTILE, NN);                            // 25 x 32
    k_logits_softmax<<<gB, 128>>>(x);

    dim3 gC(DD / 128, NN, PSPLIT);                 // 4 x 32 x 4 = 512 CTAs
    k_agg<<<gC, 128>>>(x);

    dim3 gD(KK, NN);                               // 64 x 32
    k_vlad<<<gD, 128>>>(c, out);

    k_gnorm<<<NN, 256>>>(out);
}

// round 5
// speedup vs baseline: 1.8791x; 1.2236x over previous
#include <cuda_runtime.h>
#include <math.h>
#include <stdint.h>

#define NN 32
#define DD 512
#define PP 3136
#define KK 64
#define PSPLIT 7
#define PCHUNK 448   // PP / PSPLIT, = 14 * 32 exactly
#define NTILE 25     // ceil(PP/128)

// Scratch (static device globals — no allocation)
__device__ float g_rnorm[NN * PP];                        // 401 KB
__device__ uint4 g_wf4[64 * 8 * 32 / 2];                  // permuted tf32 W frags (128 KB)
__device__ float g_soft[(size_t)NN * KK * PP];            // a*rn  (25.7 MB)
__device__ float g_aggp[(size_t)PSPLIT * NN * KK * DD];   // 28.7 MB
__device__ float g_asumt[NN * KK * NTILE];                // 200 KB

// ---------------------------------------------------------------------------
__device__ __forceinline__ uint32_t f2tf(float f) {
    uint32_t r;
    asm("cvt.rna.tf32.f32 %0, %1;" : "=r"(r) : "f"(f));
    return r;
}

__device__ __forceinline__ void mma_tf32(float c[4], const uint4& a,
                                         uint32_t b0, uint32_t b1) {
    asm("mma.sync.aligned.m16n8k8.row.col.f32.tf32.tf32.f32 "
        "{%0,%1,%2,%3}, {%4,%5,%6,%7}, {%8,%9}, {%0,%1,%2,%3};"
        : "+f"(c[0]), "+f"(c[1]), "+f"(c[2]), "+f"(c[3])
        : "r"(a.x), "r"(a.y), "r"(a.z), "r"(a.w), "r"(b0), "r"(b1));
}

// ---------------------------------------------------------------------------
// 1) inverse L2 norm per pixel (float4 over p)
// ---------------------------------------------------------------------------
__global__ void __launch_bounds__(128) k_rnorm(const float* __restrict__ x) {
    const int Q = PP / 4;
    int idx = blockIdx.x * 128 + threadIdx.x;
    if (idx >= NN * Q) return;
    int n = idx / Q, q = idx - n * Q;
    const float* base = x + (size_t)n * DD * PP + q * 4;
    float s0 = 0.f, s1 = 0.f, s2 = 0.f, s3 = 0.f;
#pragma unroll 8
    for (int d = 0; d < DD; ++d) {
        float4 v = *(const float4*)(base + (size_t)d * PP);
        s0 = fmaf(v.x, v.x, s0);
        s1 = fmaf(v.y, v.y, s1);
        s2 = fmaf(v.z, v.z, s2);
        s3 = fmaf(v.w, v.w, s3);
    }
    float4 r;
    r.x = 1.f / fmaxf(sqrtf(s0), 1e-12f);
    r.y = 1.f / fmaxf(sqrtf(s1), 1e-12f);
    r.z = 1.f / fmaxf(sqrtf(s2), 1e-12f);
    r.w = 1.f / fmaxf(sqrtf(s3), 1e-12f);
    *(float4*)(g_rnorm + (size_t)n * PP + q * 4) = r;
}

// ---------------------------------------------------------------------------
// 2) pre-permute W into tf32 B-fragments.
//    g_wf[(sg*8+nb)*32 + lane] = {W[nb*8+g][sg*8+tig], W[nb*8+g][sg*8+tig+4]}
// ---------------------------------------------------------------------------
__global__ void __launch_bounds__(256) k_wf(const float* __restrict__ w) {
    int idx = blockIdx.x * 256 + threadIdx.x;   // 0..16383
    if (idx >= 64 * 8 * 32) return;
    int lane = idx & 31;
    int nb = (idx >> 5) & 7;
    int sg = idx >> 8;
    int g = lane >> 2, tig = lane & 3;
    int k = nb * 8 + g;
    int d = sg * 8 + tig;
    uint2 v;
    v.x = f2tf(w[k * DD + d]);
    v.y = f2tf(w[k * DD + d + 4]);
    ((uint2*)g_wf4)[idx] = v;
}

// ---------------------------------------------------------------------------
// 3) logits GEMM (tf32 mma) + softmax over K, fused.
//    Block = (ptile of 128, n). C[p=128][k=64] = Xn^T @ W^T.
//    warp w: m-blocks {2w, 2w+1} (p rows w*32..w*32+31), all 8 n-blocks.
// ---------------------------------------------------------------------------
__global__ void __launch_bounds__(128) k_logits_softmax(const float* __restrict__ x) {
    const int bx = blockIdx.x;
    const int n  = blockIdx.y;
    const int p0 = bx * 128;
    const int tid  = threadIdx.x;
    const int warp = tid >> 5;
    const int lane = tid & 31;
    const int g    = lane >> 2;
    const int tig  = lane & 3;

    __shared__ uint4 axs[4][8][32];    // [kstep][mblock][lane] A frags (X)  16KB
    __shared__ uint2 bws[4][8][32];    // [kstep][nblock][lane] B frags (W)   8KB
    __shared__ float rn[128];
    __shared__ float sred[4][64];

    const int valid = (PP - p0 < 128) ? (PP - p0) : 128;   // 128 or 64 (mult of 4)

    rn[tid] = (tid < valid) ? g_rnorm[n * PP + p0 + tid] : 0.f;

    float acc[2][8][4];
#pragma unroll
    for (int mb = 0; mb < 2; ++mb)
#pragma unroll
        for (int nb = 0; nb < 8; ++nb)
#pragma unroll
            for (int r = 0; r < 4; ++r) acc[mb][nb][r] = 0.f;

    const float* xn = x + (size_t)n * DD * PP;
    __syncthreads();

    for (int d0 = 0; d0 < DD; d0 += 32) {
        // stage B: copy pre-permuted W chunk (512 uint4)
        {
            const uint4* src = g_wf4 + (d0 >> 3) * 128;   // 256 uint2 = 128 uint4 per kstep-group... (d0/8)*256 uint2 = *128 uint4
            uint4* dst = (uint4*)bws;
#pragma unroll
            for (int t = 0; t < 4; ++t)
                dst[t * 128 + tid] = src[t * 128 + tid];
        }
        // stage A: x chunk 32d x 128p, scaled by rn, scattered into frag layout
#pragma unroll
        for (int t = 0; t < 8; ++t) {
            int e = t * 128 + tid;          // 0..1023 float4 tasks
            int dl = e >> 5, grp = e & 31;  // dl: d_local, grp: p-group of 4
            float4 v = make_float4(0.f, 0.f, 0.f, 0.f);
            if (grp * 4 < valid)
                v = *(const float4*)(xn + (size_t)(d0 + dl) * PP + p0 + grp * 4);
            int s = dl >> 3, dr = dl & 7;
            int ctig = dr & 3, ch = dr >> 2;
            float vv[4] = {v.x, v.y, v.z, v.w};
#pragma unroll
            for (int i = 0; i < 4; ++i) {
                int pl = grp * 4 + i;
                int m = pl >> 4, pr = pl & 15;
                int gg = pr & 7, rh = pr >> 3;
                ((uint32_t*)&axs[s][m][gg * 4 + ctig])[rh + 2 * ch] =
                    f2tf(vv[i] * rn[pl]);
            }
        }
        __syncthreads();
#pragma unroll
        for (int s = 0; s < 4; ++s) {
            uint4 a0 = axs[s][warp * 2 + 0][lane];
            uint4 a1 = axs[s][warp * 2 + 1][lane];
#pragma unroll
            for (int nb = 0; nb < 8; ++nb) {
                uint2 b = bws[s][nb][lane];
                mma_tf32(acc[0][nb], a0, b.x, b.y);
                mma_tf32(acc[1][nb], a1, b.x, b.y);
            }
        }
        __syncthreads();
    }

    // softmax over K per pixel, in registers.
    // pixel for (mb, half): p_local = warp*32 + mb*16 + half*8 + g, regs {half*2, half*2+1}
#pragma unroll
    for (int mb = 0; mb < 2; ++mb) {
#pragma unroll
        for (int half = 0; half < 2; ++half) {
            int pl = warp * 32 + mb * 16 + half * 8 + g;
            int p = p0 + pl;
            float mx = -1e30f;
#pragma unroll
            for (int nb = 0; nb < 8; ++nb) {
                mx = fmaxf(mx, acc[mb][nb][half * 2]);
                mx = fmaxf(mx, acc[mb][nb][half * 2 + 1]);
            }
            mx = fmaxf(mx, __shfl_xor_sync(0xffffffff, mx, 1));
            mx = fmaxf(mx, __shfl_xor_sync(0xffffffff, mx, 2));
            float ssum = 0.f;
#pragma unroll
            for (int nb = 0; nb < 8; ++nb) {
                float e0 = __expf(acc[mb][nb][half * 2] - mx);
                float e1 = __expf(acc[mb][nb][half * 2 + 1] - mx);
                acc[mb][nb][half * 2] = e0;
                acc[mb][nb][half * 2 + 1] = e1;
                ssum += e0 + e1;
            }
            ssum += __shfl_xor_sync(0xffffffff, ssum, 1);
            ssum += __shfl_xor_sync(0xffffffff, ssum, 2);
            float inv = (p < PP) ? 1.f / ssum : 0.f;   // zero out invalid pixels
            float rnv = rn[pl];
            float* op = g_soft + (size_t)n * KK * PP + p;
#pragma unroll
            for (int nb = 0; nb < 8; ++nb) {
                float a0 = acc[mb][nb][half * 2] * inv;
                float a1 = acc[mb][nb][half * 2 + 1] * inv;
                acc[mb][nb][half * 2] = a0;        // keep unscaled a for asum
                acc[mb][nb][half * 2 + 1] = a1;
                if (p < PP) {
                    op[(size_t)(nb * 8 + 2 * tig) * PP]     = a0 * rnv;
                    op[(size_t)(nb * 8 + 2 * tig + 1) * PP] = a1 * rnv;
                }
            }
        }
    }

    // per-tile a_sum per k: reduce over pixels (regs 0&2 share k_even, 1&3 k_odd)
    float skE[8], skO[8];
#pragma unroll
    for (int nb = 0; nb < 8; ++nb) {
        skE[nb] = acc[0][nb][0] + acc[0][nb][2] + acc[1][nb][0] + acc[1][nb][2];
        skO[nb] = acc[0][nb][1] + acc[0][nb][3] + acc[1][nb][1] + acc[1][nb][3];
    }
#pragma unroll
    for (int mask = 4; mask <= 16; mask <<= 1)
#pragma unroll
        for (int nb = 0; nb < 8; ++nb) {
            skE[nb] += __shfl_xor_sync(0xffffffff, skE[nb], mask);
            skO[nb] += __shfl_xor_sync(0xffffffff, skO[nb], mask);
        }
    if (lane < 4) {
#pragma unroll
        for (int nb = 0; nb < 8; ++nb) {
            sred[warp][nb * 8 + 2 * lane]     = skE[nb];
            sred[warp][nb * 8 + 2 * lane + 1] = skO[nb];
        }
    }
    __syncthreads();
    if (tid < KK)
        g_asumt[(n * KK + tid) * NTILE + bx] =
            sred[0][tid] + sred[1][tid] + sred[2][tid] + sred[3][tid];
}

// ---------------------------------------------------------------------------
// 4) agg GEMM (tf32 mma): aggp[ps,n,k,d] = sum_p (a*rn)[k,p] * x[d,p]
//    Block = (dtile 128, n, psplit). C[k=64][d=128]; warp = one k m-block.
// ---------------------------------------------------------------------------
__global__ void __launch_bounds__(128) k_agg(const float* __restrict__ x) {
    const int d0 = blockIdx.x * 128;
    const int n  = blockIdx.y;
    const int ps = blockIdx.z;
    const int tid  = threadIdx.x;
    const int warp = tid >> 5;
    const int lane = tid & 31;
    const int g    = lane >> 2;
    const int tig  = lane & 3;

    __shared__ uint4 aas[4][4][32];    // [kstep][mblock(k)][lane]  A frags (soft) 8KB
    __shared__ uint2 bxs[4][16][32];   // [kstep][nblock(d)][lane]  B frags (x)   16KB

    float acc[16][4];
#pragma unroll
    for (int nb = 0; nb < 16; ++nb)
#pragma unroll
        for (int r = 0; r < 4; ++r) acc[nb][r] = 0.f;

    const float* xn = x + (size_t)n * DD * PP;
    const float* an = g_soft + (size_t)n * KK * PP;
    const int pbeg = ps * PCHUNK;

    for (int pc0 = pbeg; pc0 < pbeg + PCHUNK; pc0 += 32) {
        __syncthreads();
        // stage A (soft a*rn): 64k x 32p -> frag layout
#pragma unroll
        for (int t = 0; t < 4; ++t) {
            int e = t * 128 + tid;          // 0..511 float4 tasks
            int k = e >> 3, grp = e & 7;
            float4 v = *(const float4*)(an + (size_t)k * PP + pc0 + grp * 4);
            int m = k >> 4, kr = k & 15;
            int gg = kr & 7, rh = kr >> 3;
            float vv[4] = {v.x, v.y, v.z, v.w};
#pragma unroll
            for (int i = 0; i < 4; ++i) {
                int pl = grp * 4 + i;
                int s = pl >> 3, pr = pl & 7;
                int ctig = pr & 3, ch = pr >> 2;
                ((uint32_t*)&aas[s][m][gg * 4 + ctig])[rh + 2 * ch] = f2tf(vv[i]);
            }
        }
        // stage B (x): 128d x 32p -> frag layout
#pragma unroll
        for (int t = 0; t < 8; ++t) {
            int e = t * 128 + tid;          // 0..1023 float4 tasks
            int dl = e >> 3, grp = e & 7;
            float4 v = *(const float4*)(xn + (size_t)(d0 + dl) * PP + pc0 + grp * 4);
            int nb = dl >> 3, dg = dl & 7;
            float vv[4] = {v.x, v.y, v.z, v.w};
#pragma unroll
            for (int i = 0; i < 4; ++i) {
                int pl = grp * 4 + i;
                int s = pl >> 3, pr = pl & 7;
                int btig = pr & 3, half = pr >> 2;
                ((uint32_t*)&bxs[s][nb][dg * 4 + btig])[half] = f2tf(vv[i]);
            }
        }
        __syncthreads();
#pragma unroll
        for (int s = 0; s < 4; ++s) {
            uint4 a = aas[s][warp][lane];
#pragma unroll
            for (int nb = 0; nb < 16; ++nb) {
                uint2 b = bxs[s][nb][lane];
                mma_tf32(acc[nb], a, b.x, b.y);
            }
        }
    }

    // epilogue: k = warp*16 + g (+8), d = d0 + nb*8 + 2*tig (+1)
    float* op = g_aggp + ((size_t)(ps * NN + n) * KK + warp * 16) * DD + d0;
#pragma unroll
    for (int nb = 0; nb < 16; ++nb) {
        int d = nb * 8 + 2 * tig;
        *(float2*)&op[(size_t)g * DD + d]       = make_float2(acc[nb][0], acc[nb][1]);
        *(float2*)&op[(size_t)(g + 8) * DD + d] = make_float2(acc[nb][2], acc[nb][3]);
    }
}

// ---------------------------------------------------------------------------
// 5) vlad: a_sum (tile partials) + (agg - a_sum*c) + intra L2 norm
// ---------------------------------------------------------------------------
__global__ void __launch_bounds__(128) k_vlad(const float* __restrict__ centroids,
                                              float* __restrict__ out) {
    const int k = blockIdx.x;
    const int n = blockIdx.y;
    const int tid = threadIdx.x;
    __shared__ float red[128];

    float asum = 0.f;
    const float* at = g_asumt + (n * KK + k) * NTILE;
#pragma unroll
    for (int t = 0; t < NTILE; ++t) asum += at[t];

    float v[4];
    float ss = 0.f;
#pragma unroll
    for (int j = 0; j < 4; ++j) {
        int d = j * 128 + tid;
        float a = 0.f;
#pragma unroll
        for (int ps = 0; ps < PSPLIT; ++ps)
            a += g_aggp[(((size_t)ps * NN + n) * KK + k) * DD + d];
        v[j] = a - asum * centroids[k * DD + d];
        ss = fmaf(v[j], v[j], ss);
    }
    red[tid] = ss;
    __syncthreads();
    for (int w = 64; w > 0; w >>= 1) {
        if (tid < w) red[tid] += red[tid + w];
        __syncthreads();
    }
    float rinv = 1.f / fmaxf(sqrtf(red[0]), 1e-12f);
    const size_t base = ((size_t)n * KK + k) * DD;
#pragma unroll
    for (int j = 0; j < 4; ++j)
        out[base + j * 128 + tid] = v[j] * rinv;
}

// ---------------------------------------------------------------------------
// 6) global L2 norm per n over K*D
// ---------------------------------------------------------------------------
__global__ void __launch_bounds__(256) k_gnorm(float* __restrict__ out) {
    const int n = blockIdx.x;
    const int tid = threadIdx.x;
    __shared__ float red[256];
    float* row = out + (size_t)n * KK * DD;
    float ss = 0.f;
    for (int i = tid; i < KK * DD; i += 256) {
        float v = row[i];
        ss = fmaf(v, v, ss);
    }
    red[tid] = ss;
    __syncthreads();
    for (int w = 128; w > 0; w >>= 1) {
        if (tid < w) red[tid] += red[tid + w];
        __syncthreads();
    }
    float rinv = 1.f / fmaxf(sqrtf(red[0]), 1e-12f);
    for (int i = tid; i < KK * DD; i += 256) row[i] *= rinv;
}

// ---------------------------------------------------------------------------
extern "C" void kernel_launch(void* const* d_in, const int* in_sizes, int n_in,
                              void* d_out, int out_size) {
    const float* x = (const float*)d_in[0];        // (32, 512, 56, 56)
    const float* w = (const float*)d_in[1];        // (64, 512)
    const float* c = (const float*)d_in[2];        // (64, 512)
    float* out = (float*)d_out;                    // (32, 32768) fp32

    k_rnorm<<<(NN * (PP / 4) + 127) / 128, 128>>>(x);
    k_wf<<<(64 * 8 * 32 + 255) / 256, 256>>>(w);

    dim3 gB(NTILE, NN);                            // 25 x 32
    k_logits_softmax<<<gB, 128>>>(x);

    dim3 gC(DD / 128, NN, PSPLIT);                 // 4 x 32 x 7 = 896 CTAs
    k_agg<<<gC, 128>>>(x);

    dim3 gD(KK, NN);                               // 64 x 32
    k_vlad<<<gD, 128>>>(c, out);

    k_gnorm<<<NN, 256>>>(out);
}

// round 6
// speedup vs baseline: 3.3997x; 1.8092x over previous
#include <cuda_runtime.h>
#include <cuda_bf16.h>
#include <math.h>
#include <stdint.h>

#define NN 32
#define DD 512
#define PP 3136
#define KK 64
#define PSPLIT 7
#define PCHUNK 448   // PP / PSPLIT = 14 * 32 exactly
#define NTILE 25     // ceil(PP/128)

// Scratch (static device globals — no allocation)
__device__ float g_rnorm[NN * PP];                                   // 401 KB
__device__ __align__(16) __nv_bfloat16 g_wbf[KK * DD];               // 64 KB
__device__ __align__(16) __nv_bfloat16 g_soft[(size_t)NN * KK * PP]; // a*rn, 12.8 MB
__device__ float g_aggp[(size_t)PSPLIT * NN * KK * DD];              // 28.7 MB
__device__ float g_asumt[NN * KK * NTILE];                           // 200 KB

// ---------------------------------------------------------------------------
__device__ __forceinline__ uint32_t pack_bf2(float lo, float hi) {
    uint32_t r;
    asm("cvt.rn.bf16x2.f32 %0, %1, %2;" : "=r"(r) : "f"(hi), "f"(lo));
    return r;
}

__device__ __forceinline__ void ldm_x4(uint32_t r[4], uint32_t addr) {
    asm volatile("ldmatrix.sync.aligned.m8n8.x4.shared.b16 {%0,%1,%2,%3}, [%4];"
                 : "=r"(r[0]), "=r"(r[1]), "=r"(r[2]), "=r"(r[3]) : "r"(addr));
}
__device__ __forceinline__ void ldm_x4t(uint32_t r[4], uint32_t addr) {
    asm volatile("ldmatrix.sync.aligned.m8n8.x4.trans.shared.b16 {%0,%1,%2,%3}, [%4];"
                 : "=r"(r[0]), "=r"(r[1]), "=r"(r[2]), "=r"(r[3]) : "r"(addr));
}
__device__ __forceinline__ void mma_bf16(float c[4], const uint32_t a[4],
                                         uint32_t b0, uint32_t b1) {
    asm volatile("mma.sync.aligned.m16n8k16.row.col.f32.bf16.bf16.f32 "
                 "{%0,%1,%2,%3}, {%4,%5,%6,%7}, {%8,%9}, {%0,%1,%2,%3};"
                 : "+f"(c[0]), "+f"(c[1]), "+f"(c[2]), "+f"(c[3])
                 : "r"(a[0]), "r"(a[1]), "r"(a[2]), "r"(a[3]), "r"(b0), "r"(b1));
}

// ---------------------------------------------------------------------------
// 1) inverse L2 norm per pixel (float4 over p)
// ---------------------------------------------------------------------------
__global__ void __launch_bounds__(128) k_rnorm(const float* __restrict__ x) {
    const int Q = PP / 4;
    int idx = blockIdx.x * 128 + threadIdx.x;
    if (idx >= NN * Q) return;
    int n = idx / Q, q = idx - n * Q;
    const float* base = x + (size_t)n * DD * PP + q * 4;
    float s0 = 0.f, s1 = 0.f, s2 = 0.f, s3 = 0.f;
#pragma unroll 8
    for (int d = 0; d < DD; ++d) {
        float4 v = *(const float4*)(base + (size_t)d * PP);
        s0 = fmaf(v.x, v.x, s0);
        s1 = fmaf(v.y, v.y, s1);
        s2 = fmaf(v.z, v.z, s2);
        s3 = fmaf(v.w, v.w, s3);
    }
    float4 r;
    r.x = 1.f / fmaxf(sqrtf(s0), 1e-12f);
    r.y = 1.f / fmaxf(sqrtf(s1), 1e-12f);
    r.z = 1.f / fmaxf(sqrtf(s2), 1e-12f);
    r.w = 1.f / fmaxf(sqrtf(s3), 1e-12f);
    *(float4*)(g_rnorm + (size_t)n * PP + q * 4) = r;
}

// ---------------------------------------------------------------------------
// 2) convert W to bf16 (row-major [k][d])
// ---------------------------------------------------------------------------
__global__ void __launch_bounds__(256) k_wbf(const float* __restrict__ w) {
    int i = blockIdx.x * 256 + threadIdx.x;   // bf16x2 index
    if (i >= KK * DD / 2) return;
    ((uint32_t*)g_wbf)[i] = pack_bf2(w[2 * i], w[2 * i + 1]);
}

// ---------------------------------------------------------------------------
// 3) logits GEMM (bf16 mma + ldmatrix) + softmax over K, fused.
//    C[p=128][k=64]; A = x̂[p][d] via ldmatrix.trans of x_s[d][p];
//    B = w[k][d] via ldmatrix of w_s[k][d]. 16 d-chunks of 32.
// ---------------------------------------------------------------------------
__global__ void __launch_bounds__(128) k_logits_softmax(const float* __restrict__ x) {
    const int bx = blockIdx.x;
    const int n  = blockIdx.y;
    const int p0 = bx * 128;
    const int tid  = threadIdx.x;
    const int warp = tid >> 5;
    const int lane = tid & 31;
    const int g    = lane >> 2;
    const int tig  = lane & 3;

    __shared__ __align__(16) uint16_t x_s[2][32 * 136];   // [d][p] pitch 136 bf16 (272B)
    __shared__ __align__(16) uint16_t w_s[2][64 * 40];    // [k][d] pitch 40 bf16 (80B)
    __shared__ float rn[128];
    __shared__ float sred[4][64];

    const int valid = (PP - p0 < 128) ? (PP - p0) : 128;   // 128 or 64

    rn[tid] = (tid < valid) ? g_rnorm[n * PP + p0 + tid] : 0.f;
    __syncthreads();

    float acc[2][8][4];
#pragma unroll
    for (int mb = 0; mb < 2; ++mb)
#pragma unroll
        for (int nb = 0; nb < 8; ++nb)
#pragma unroll
            for (int r = 0; r < 4; ++r) acc[mb][nb][r] = 0.f;

    const float* xn = x + (size_t)n * DD * PP;

    // staging registers
    float4 vx[4][2];   // 4 tasks x 2 float4 (8 p each)
    uint4  vw[2];      // 2 LDG.128 of w bf16

    // task maps (constant per thread)
    // x: 512 tasks = 32 rows x 16 octs; 4/thread
    // w: 256 tasks = 64 rows x 4 c;     2/thread

#define LDG_LOGITS(d0)                                                          \
    {                                                                           \
        _Pragma("unroll")                                                       \
        for (int t4 = 0; t4 < 4; ++t4) {                                        \
            int e = t4 * 128 + tid, row = e >> 4, oct = e & 15;                 \
            if (oct * 8 < valid) {                                              \
                const float* s = xn + (size_t)((d0) + row) * PP + p0 + oct * 8; \
                vx[t4][0] = *(const float4*)s;                                  \
                vx[t4][1] = *(const float4*)(s + 4);                            \
            } else {                                                            \
                vx[t4][0] = make_float4(0.f, 0.f, 0.f, 0.f);                    \
                vx[t4][1] = make_float4(0.f, 0.f, 0.f, 0.f);                    \
            }                                                                   \
        }                                                                       \
        _Pragma("unroll")                                                       \
        for (int t2 = 0; t2 < 2; ++t2) {                                        \
            int e = t2 * 128 + tid, row = e >> 2, c = e & 3;                    \
            vw[t2] = *(const uint4*)(g_wbf + row * DD + (d0) + c * 8);          \
        }                                                                       \
    }

#define STS_LOGITS(buf)                                                         \
    {                                                                           \
        _Pragma("unroll")                                                       \
        for (int t4 = 0; t4 < 4; ++t4) {                                        \
            int e = t4 * 128 + tid, row = e >> 4, oct = e & 15;                 \
            float r0 = rn[oct * 8 + 0], r1 = rn[oct * 8 + 1];                   \
            float r2 = rn[oct * 8 + 2], r3 = rn[oct * 8 + 3];                   \
            float r4 = rn[oct * 8 + 4], r5 = rn[oct * 8 + 5];                   \
            float r6 = rn[oct * 8 + 6], r7 = rn[oct * 8 + 7];                   \
            uint4 o;                                                            \
            o.x = pack_bf2(vx[t4][0].x * r0, vx[t4][0].y * r1);                 \
            o.y = pack_bf2(vx[t4][0].z * r2, vx[t4][0].w * r3);                 \
            o.z = pack_bf2(vx[t4][1].x * r4, vx[t4][1].y * r5);                 \
            o.w = pack_bf2(vx[t4][1].z * r6, vx[t4][1].w * r7);                 \
            *(uint4*)&x_s[buf][row * 136 + oct * 8] = o;                        \
        }                                                                       \
        _Pragma("unroll")                                                       \
        for (int t2 = 0; t2 < 2; ++t2) {                                        \
            int e = t2 * 128 + tid, row = e >> 2, c = e & 3;                    \
            *(uint4*)&w_s[buf][row * 40 + c * 8] = vw[t2];                      \
        }                                                                       \
    }

    LDG_LOGITS(0);
    STS_LOGITS(0);
    __syncthreads();

    for (int ch = 0; ch < 16; ++ch) {
        int buf = ch & 1;
        if (ch < 15) LDG_LOGITS((ch + 1) * 32);
#pragma unroll
        for (int s = 0; s < 2; ++s) {
            uint32_t afr[2][4];
#pragma unroll
            for (int mb = 0; mb < 2; ++mb) {
                int row  = s * 16 + (lane & 7) + ((lane >> 4) & 1) * 8;
                int pcol = (warp * 2 + mb) * 16 + ((lane >> 3) & 1) * 8;
                uint32_t ad = (uint32_t)__cvta_generic_to_shared(
                    &x_s[buf][row * 136 + pcol]);
                ldm_x4t(afr[mb], ad);
            }
#pragma unroll
            for (int qb = 0; qb < 4; ++qb) {
                int row = qb * 16 + (lane & 7) + ((lane >> 3) & 1) * 8;
                uint32_t bd = (uint32_t)__cvta_generic_to_shared(
                    &w_s[buf][row * 40 + s * 16 + ((lane >> 4) & 1) * 8]);
                uint32_t bfr[4];
                ldm_x4(bfr, bd);
#pragma unroll
                for (int mb = 0; mb < 2; ++mb) {
                    mma_bf16(acc[mb][2 * qb],     afr[mb], bfr[0], bfr[2]);
                    mma_bf16(acc[mb][2 * qb + 1], afr[mb], bfr[1], bfr[3]);
                }
            }
        }
        if (ch < 15) STS_LOGITS(buf ^ 1);
        __syncthreads();
    }

    // softmax over K per pixel, in registers.
    // (mb, half): p_local = warp*32 + mb*16 + half*8 + g, regs {half*2, half*2+1}
#pragma unroll
    for (int mb = 0; mb < 2; ++mb) {
#pragma unroll
        for (int half = 0; half < 2; ++half) {
            int pl = warp * 32 + mb * 16 + half * 8 + g;
            int p = p0 + pl;
            float mx = -1e30f;
#pragma unroll
            for (int nb = 0; nb < 8; ++nb) {
                mx = fmaxf(mx, acc[mb][nb][half * 2]);
                mx = fmaxf(mx, acc[mb][nb][half * 2 + 1]);
            }
            mx = fmaxf(mx, __shfl_xor_sync(0xffffffff, mx, 1));
            mx = fmaxf(mx, __shfl_xor_sync(0xffffffff, mx, 2));
            float ssum = 0.f;
#pragma unroll
            for (int nb = 0; nb < 8; ++nb) {
                float e0 = __expf(acc[mb][nb][half * 2] - mx);
                float e1 = __expf(acc[mb][nb][half * 2 + 1] - mx);
                acc[mb][nb][half * 2] = e0;
                acc[mb][nb][half * 2 + 1] = e1;
                ssum += e0 + e1;
            }
            ssum += __shfl_xor_sync(0xffffffff, ssum, 1);
            ssum += __shfl_xor_sync(0xffffffff, ssum, 2);
            float inv = (p < PP) ? 1.f / ssum : 0.f;
            float rnv = rn[pl];
            __nv_bfloat16* op = g_soft + (size_t)n * KK * PP + p;
#pragma unroll
            for (int nb = 0; nb < 8; ++nb) {
                float a0 = acc[mb][nb][half * 2] * inv;
                float a1 = acc[mb][nb][half * 2 + 1] * inv;
                acc[mb][nb][half * 2] = a0;
                acc[mb][nb][half * 2 + 1] = a1;
                if (p < PP) {
                    op[(size_t)(nb * 8 + 2 * tig) * PP]     = __float2bfloat16_rn(a0 * rnv);
                    op[(size_t)(nb * 8 + 2 * tig + 1) * PP] = __float2bfloat16_rn(a1 * rnv);
                }
            }
        }
    }

    // per-tile a_sum per k (fp32)
    float skE[8], skO[8];
#pragma unroll
    for (int nb = 0; nb < 8; ++nb) {
        skE[nb] = acc[0][nb][0] + acc[0][nb][2] + acc[1][nb][0] + acc[1][nb][2];
        skO[nb] = acc[0][nb][1] + acc[0][nb][3] + acc[1][nb][1] + acc[1][nb][3];
    }
#pragma unroll
    for (int mask = 4; mask <= 16; mask <<= 1)
#pragma unroll
        for (int nb = 0; nb < 8; ++nb) {
            skE[nb] += __shfl_xor_sync(0xffffffff, skE[nb], mask);
            skO[nb] += __shfl_xor_sync(0xffffffff, skO[nb], mask);
        }
    if (lane < 4) {
#pragma unroll
        for (int nb = 0; nb < 8; ++nb) {
            sred[warp][nb * 8 + 2 * lane]     = skE[nb];
            sred[warp][nb * 8 + 2 * lane + 1] = skO[nb];
        }
    }
    __syncthreads();
    if (tid < KK)
        g_asumt[(n * KK + tid) * NTILE + bx] =
            sred[0][tid] + sred[1][tid] + sred[2][tid] + sred[3][tid];
}

// ---------------------------------------------------------------------------
// 4) agg GEMM (bf16 mma + ldmatrix): aggp[ps,n,k,d] = sum_p a[k][p] * x[d][p]
//    C[kc=64][d=128]; A = a_s[k][p] (natural), B = x_s[d][p] (natural).
//    14 p-chunks of 32. warp -> m16 block (kc = warp*16), 16 n-blocks of d8.
// ---------------------------------------------------------------------------
__global__ void __launch_bounds__(128) k_agg(const float* __restrict__ x) {
    const int d0 = blockIdx.x * 128;
    const int n  = blockIdx.y;
    const int ps = blockIdx.z;
    const int tid  = threadIdx.x;
    const int warp = tid >> 5;
    const int lane = tid & 31;

    __shared__ __align__(16) uint16_t a_s[2][64 * 40];    // [k][p] pitch 40 (80B)
    __shared__ __align__(16) uint16_t x_s[2][128 * 40];   // [d][p] pitch 40 (80B)

    float acc[16][4];
#pragma unroll
    for (int nb = 0; nb < 16; ++nb)
#pragma unroll
        for (int r = 0; r < 4; ++r) acc[nb][r] = 0.f;

    const float* xn = x + (size_t)n * DD * PP;
    const __nv_bfloat16* an = g_soft + (size_t)n * KK * PP;
    const int pbeg = ps * PCHUNK;

    float4 vx[4][2];   // x: 512 tasks (128 rows x 4 octs), 4/thread
    uint4  va[2];      // a: 256 tasks (64 rows x 4 c), 2/thread, bf16 copy

#define LDG_AGG(pc0)                                                            \
    {                                                                           \
        _Pragma("unroll")                                                       \
        for (int t4 = 0; t4 < 4; ++t4) {                                        \
            int e = t4 * 128 + tid, row = e >> 2, oct = e & 3;                  \
            const float* s = xn + (size_t)(d0 + row) * PP + (pc0) + oct * 8;    \
            vx[t4][0] = *(const float4*)s;                                      \
            vx[t4][1] = *(const float4*)(s + 4);                                \
        }                                                                       \
        _Pragma("unroll")                                                       \
        for (int t2 = 0; t2 < 2; ++t2) {                                        \
            int e = t2 * 128 + tid, row = e >> 2, c = e & 3;                    \
            va[t2] = *(const uint4*)(an + (size_t)row * PP + (pc0) + c * 8);    \
        }                                                                       \
    }

#define STS_AGG(buf)                                                            \
    {                                                                           \
        _Pragma("unroll")                                                       \
        for (int t4 = 0; t4 < 4; ++t4) {                                        \
            int e = t4 * 128 + tid, row = e >> 2, oct = e & 3;                  \
            uint4 o;                                                            \
            o.x = pack_bf2(vx[t4][0].x, vx[t4][0].y);                           \
            o.y = pack_bf2(vx[t4][0].z, vx[t4][0].w);                           \
            o.z = pack_bf2(vx[t4][1].x, vx[t4][1].y);                           \
            o.w = pack_bf2(vx[t4][1].z, vx[t4][1].w);                           \
            *(uint4*)&x_s[buf][row * 40 + oct * 8] = o;                         \
        }                                                                       \
        _Pragma("unroll")                                                       \
        for (int t2 = 0; t2 < 2; ++t2) {                                        \
            int e = t2 * 128 + tid, row = e >> 2, c = e & 3;                    \
            *(uint4*)&a_s[buf][row * 40 + c * 8] = va[t2];                      \
        }                                                                       \
    }

    LDG_AGG(pbeg);
    STS_AGG(0);
    __syncthreads();

    const int NCH = PCHUNK / 32;   // 14
    for (int ch = 0; ch < NCH; ++ch) {
        int buf = ch & 1;
        if (ch < NCH - 1) LDG_AGG(pbeg + (ch + 1) * 32);
#pragma unroll
        for (int s = 0; s < 2; ++s) {
            int rbase = (lane & 7) + ((lane >> 3) & 1) * 8;
            int cofs  = s * 16 + ((lane >> 4) & 1) * 8;
            uint32_t afr[4];
            {
                uint32_t ad = (uint32_t)__cvta_generic_to_shared(
                    &a_s[buf][(warp * 16 + rbase) * 40 + cofs]);
                ldm_x4(afr, ad);
            }
#pragma unroll
            for (int pb = 0; pb < 8; ++pb) {
                uint32_t bd = (uint32_t)__cvta_generic_to_shared(
                    &x_s[buf][(pb * 16 + rbase) * 40 + cofs]);
                uint32_t bfr[4];
                ldm_x4(bfr, bd);
                mma_bf16(acc[2 * pb],     afr, bfr[0], bfr[2]);
                mma_bf16(acc[2 * pb + 1], afr, bfr[1], bfr[3]);
            }
        }
        if (ch < NCH - 1) STS_AGG(buf ^ 1);
        __syncthreads();
    }

    // epilogue: kc = warp*16 + lane/4 (+8), d = d0 + nb*8 + (lane%4)*2
    float* op = g_aggp + ((size_t)(ps * NN + n) * KK + warp * 16) * DD + d0;
    int r = lane >> 2, cq = (lane & 3) * 2;
#pragma unroll
    for (int nb = 0; nb < 16; ++nb) {
        int d = nb * 8 + cq;
        *(float2*)&op[(size_t)r * DD + d]       = make_float2(acc[nb][0], acc[nb][1]);
        *(float2*)&op[(size_t)(r + 8) * DD + d] = make_float2(acc[nb][2], acc[nb][3]);
    }
}

// ---------------------------------------------------------------------------
// 5) vlad: a_sum (tile partials) + (agg - a_sum*c) + intra L2 norm
// ---------------------------------------------------------------------------
__global__ void __launch_bounds__(128) k_vlad(const float* __restrict__ centroids,
                                              float* __restrict__ out) {
    const int k = blockIdx.x;
    const int n = blockIdx.y;
    const int tid = threadIdx.x;
    __shared__ float red[128];

    float asum = 0.f;
    const float* at = g_asumt + (n * KK + k) * NTILE;
#pragma unroll
    for (int t = 0; t < NTILE; ++t) asum += at[t];

    float v[4];
    float ss = 0.f;
#pragma unroll
    for (int j = 0; j < 4; ++j) {
        int d = j * 128 + tid;
        float a = 0.f;
#pragma unroll
        for (int ps = 0; ps < PSPLIT; ++ps)
            a += g_aggp[(((size_t)ps * NN + n) * KK + k) * DD + d];
        v[j] = a - asum * centroids[k * DD + d];
        ss = fmaf(v[j], v[j], ss);
    }
    red[tid] = ss;
    __syncthreads();
    for (int w = 64; w > 0; w >>= 1) {
        if (tid < w) red[tid] += red[tid + w];
        __syncthreads();
    }
    float rinv = 1.f / fmaxf(sqrtf(red[0]), 1e-12f);
    const size_t base = ((size_t)n * KK + k) * DD;
#pragma unroll
    for (int j = 0; j < 4; ++j)
        out[base + j * 128 + tid] = v[j] * rinv;
}

// ---------------------------------------------------------------------------
// 6) global L2 norm per n over K*D
// ---------------------------------------------------------------------------
__global__ void __launch_bounds__(256) k_gnorm(float* __restrict__ out) {
    const int n = blockIdx.x;
    const int tid = threadIdx.x;
    __shared__ float red[256];
    float* row = out + (size_t)n * KK * DD;
    float ss = 0.f;
    for (int i = tid; i < KK * DD; i += 256) {
        float v = row[i];
        ss = fmaf(v, v, ss);
    }
    red[tid] = ss;
    __syncthreads();
    for (int w = 128; w > 0; w >>= 1) {
        if (tid < w) red[tid] += red[tid + w];
        __syncthreads();
    }
    float rinv = 1.f / fmaxf(sqrtf(red[0]), 1e-12f);
    for (int i = tid; i < KK * DD; i += 256) row[i] *= rinv;
}

// ---------------------------------------------------------------------------
extern "C" void kernel_launch(void* const* d_in, const int* in_sizes, int n_in,
                              void* d_out, int out_size) {
    const float* x = (const float*)d_in[0];        // (32, 512, 56, 56)
    const float* w = (const float*)d_in[1];        // (64, 512)
    const float* c = (const float*)d_in[2];        // (64, 512)
    float* out = (float*)d_out;                    // (32, 32768) fp32

    k_rnorm<<<(NN * (PP / 4) + 127) / 128, 128>>>(x);
    k_wbf<<<(KK * DD / 2 + 255) / 256, 256>>>(w);

    dim3 gB(NTILE, NN);                            // 25 x 32
    k_logits_softmax<<<gB, 128>>>(x);

    dim3 gC(DD / 128, NN, PSPLIT);                 // 4 x 32 x 7 = 896 CTAs
    k_agg<<<gC, 128>>>(x);

    dim3 gD(KK, NN);                               // 64 x 32
    k_vlad<<<gD, 128>>>(c, out);

    k_gnorm<<<NN, 256>>>(out);
}

// round 7
// speedup vs baseline: 5.6574x; 1.6641x over previous
#include <cuda_runtime.h>
#include <cuda_bf16.h>
#include <math.h>
#include <stdint.h>

#define NN 32
#define DD 512
#define PP 3136
#define KK 64
#define PSPLIT 7
#define PCHUNK 448   // PP / PSPLIT = 14 * 32 exactly
#define NTILE 25     // ceil(PP/128)

// Scratch (static device globals — no allocation)
__device__ __align__(16) __nv_bfloat16 g_wbf[KK * DD];               // 64 KB
__device__ __align__(16) __nv_bfloat16 g_soft[(size_t)NN * KK * PP]; // a*rn, 12.8 MB
__device__ float g_aggp[(size_t)PSPLIT * NN * KK * DD];              // 28.7 MB
__device__ float g_asumt[NN * KK * NTILE];                           // 200 KB

// ---------------------------------------------------------------------------
__device__ __forceinline__ uint32_t pack_bf2(float lo, float hi) {
    uint32_t r;
    asm("cvt.rn.bf16x2.f32 %0, %1, %2;" : "=r"(r) : "f"(hi), "f"(lo));
    return r;
}
__device__ __forceinline__ void ldm_x4(uint32_t r[4], uint32_t addr) {
    asm volatile("ldmatrix.sync.aligned.m8n8.x4.shared.b16 {%0,%1,%2,%3}, [%4];"
                 : "=r"(r[0]), "=r"(r[1]), "=r"(r[2]), "=r"(r[3]) : "r"(addr));
}
__device__ __forceinline__ void ldm_x4t(uint32_t r[4], uint32_t addr) {
    asm volatile("ldmatrix.sync.aligned.m8n8.x4.trans.shared.b16 {%0,%1,%2,%3}, [%4];"
                 : "=r"(r[0]), "=r"(r[1]), "=r"(r[2]), "=r"(r[3]) : "r"(addr));
}
__device__ __forceinline__ void mma_bf16(float c[4], const uint32_t a[4],
                                         uint32_t b0, uint32_t b1) {
    asm volatile("mma.sync.aligned.m16n8k16.row.col.f32.bf16.bf16.f32 "
                 "{%0,%1,%2,%3}, {%4,%5,%6,%7}, {%8,%9}, {%0,%1,%2,%3};"
                 : "+f"(c[0]), "+f"(c[1]), "+f"(c[2]), "+f"(c[3])
                 : "r"(a[0]), "r"(a[1]), "r"(a[2]), "r"(a[3]), "r"(b0), "r"(b1));
}
__device__ __forceinline__ void cp_async16(uint32_t saddr, const void* g) {
    asm volatile("cp.async.ca.shared.global [%0], [%1], 16;" :: "r"(saddr), "l"(g));
}
#define CP_COMMIT() asm volatile("cp.async.commit_group;")
#define CP_WAIT0()  asm volatile("cp.async.wait_group 0;")

// ---------------------------------------------------------------------------
// 1) convert W to bf16 (row-major [k][d])
// ---------------------------------------------------------------------------
__global__ void __launch_bounds__(256) k_wbf(const float* __restrict__ w) {
    int i = blockIdx.x * 256 + threadIdx.x;
    if (i >= KK * DD / 2) return;
    ((uint32_t*)g_wbf)[i] = pack_bf2(w[2 * i], w[2 * i + 1]);
}

// ---------------------------------------------------------------------------
// 2) fused: per-pixel L2 norm + logits GEMM (bf16 mma) + softmax over K.
//    GEMM on UNNORMALIZED x; logits scaled by rn[p] post-GEMM (rn is a
//    per-pixel scalar so (W·x̂) = (W·x)·rn). ||x||² accumulated during staging.
// ---------------------------------------------------------------------------
__global__ void __launch_bounds__(128) k_logits_softmax(const float* __restrict__ x) {
    const int bx = blockIdx.x;
    const int n  = blockIdx.y;
    const int p0 = bx * 128;
    const int tid  = threadIdx.x;
    const int warp = tid >> 5;
    const int lane = tid & 31;
    const int g    = lane >> 4 ? 0 : 0;   // placeholder (recomputed below)
    const int gq   = lane >> 2;
    const int tig  = lane & 3;

    __shared__ __align__(16) uint16_t x_s[2][32 * 136];   // [d][p] pitch 136 (272B)
    __shared__ __align__(16) uint16_t w_s[2][64 * 40];    // [k][d] pitch 40 (80B)
    __shared__ float rn[128];
    __shared__ float sred[4][64];
    __shared__ float sqs[8][128];

    const int valid = (PP - p0 < 128) ? (PP - p0) : 128;   // 128 or 64

    float acc[2][8][4];
#pragma unroll
    for (int mb = 0; mb < 2; ++mb)
#pragma unroll
        for (int nb = 0; nb < 8; ++nb)
#pragma unroll
            for (int r = 0; r < 4; ++r) acc[mb][nb][r] = 0.f;

    float sq[8];
#pragma unroll
    for (int i = 0; i < 8; ++i) sq[i] = 0.f;

    const float* xn = x + (size_t)n * DD * PP;
    float4 vx[4][2];   // x: 512 tasks = 32 rows x 16 octs; 4/thread; oct = tid&15 fixed

#define LDG_X(d0)                                                               \
    {                                                                           \
        _Pragma("unroll")                                                       \
        for (int t4 = 0; t4 < 4; ++t4) {                                        \
            int e = t4 * 128 + tid, row = e >> 4, oct = e & 15;                 \
            if (oct * 8 < valid) {                                              \
                const float* s = xn + (size_t)((d0) + row) * PP + p0 + oct * 8; \
                vx[t4][0] = *(const float4*)s;                                  \
                vx[t4][1] = *(const float4*)(s + 4);                            \
            } else {                                                            \
                vx[t4][0] = make_float4(0.f, 0.f, 0.f, 0.f);                    \
                vx[t4][1] = make_float4(0.f, 0.f, 0.f, 0.f);                    \
            }                                                                   \
        }                                                                       \
    }

#define STS_X(buf)                                                              \
    {                                                                           \
        _Pragma("unroll")                                                       \
        for (int t4 = 0; t4 < 4; ++t4) {                                        \
            int e = t4 * 128 + tid, row = e >> 4, oct = e & 15;                 \
            sq[0] = fmaf(vx[t4][0].x, vx[t4][0].x, sq[0]);                      \
            sq[1] = fmaf(vx[t4][0].y, vx[t4][0].y, sq[1]);                      \
            sq[2] = fmaf(vx[t4][0].z, vx[t4][0].z, sq[2]);                      \
            sq[3] = fmaf(vx[t4][0].w, vx[t4][0].w, sq[3]);                      \
            sq[4] = fmaf(vx[t4][1].x, vx[t4][1].x, sq[4]);                      \
            sq[5] = fmaf(vx[t4][1].y, vx[t4][1].y, sq[5]);                      \
            sq[6] = fmaf(vx[t4][1].z, vx[t4][1].z, sq[6]);                      \
            sq[7] = fmaf(vx[t4][1].w, vx[t4][1].w, sq[7]);                      \
            uint4 o;                                                            \
            o.x = pack_bf2(vx[t4][0].x, vx[t4][0].y);                           \
            o.y = pack_bf2(vx[t4][0].z, vx[t4][0].w);                           \
            o.z = pack_bf2(vx[t4][1].x, vx[t4][1].y);                           \
            o.w = pack_bf2(vx[t4][1].z, vx[t4][1].w);                           \
            *(uint4*)&x_s[buf][row * 136 + oct * 8] = o;                        \
        }                                                                       \
    }

#define CPA_W(d0, buf)                                                          \
    {                                                                           \
        _Pragma("unroll")                                                       \
        for (int t2 = 0; t2 < 2; ++t2) {                                        \
            int e = t2 * 128 + tid, row = e >> 2, c = e & 3;                    \
            cp_async16((uint32_t)__cvta_generic_to_shared(                      \
                           &w_s[buf][row * 40 + c * 8]),                        \
                       g_wbf + row * DD + (d0) + c * 8);                        \
        }                                                                       \
    }

    CPA_W(0, 0);
    CP_COMMIT();
    LDG_X(0);
    STS_X(0);
    CP_WAIT0();
    __syncthreads();

    for (int ch = 0; ch < 16; ++ch) {
        int buf = ch & 1;
        if (ch < 15) {
            LDG_X((ch + 1) * 32);
            CPA_W((ch + 1) * 32, buf ^ 1);
            CP_COMMIT();
        }
#pragma unroll
        for (int s = 0; s < 2; ++s) {
            uint32_t afr[2][4];
#pragma unroll
            for (int mb = 0; mb < 2; ++mb) {
                int row  = s * 16 + (lane & 7) + ((lane >> 4) & 1) * 8;
                int pcol = (warp * 2 + mb) * 16 + ((lane >> 3) & 1) * 8;
                uint32_t ad = (uint32_t)__cvta_generic_to_shared(
                    &x_s[buf][row * 136 + pcol]);
                ldm_x4t(afr[mb], ad);
            }
#pragma unroll
            for (int qb = 0; qb < 4; ++qb) {
                int row = qb * 16 + (lane & 7) + ((lane >> 3) & 1) * 8;
                uint32_t bd = (uint32_t)__cvta_generic_to_shared(
                    &w_s[buf][row * 40 + s * 16 + ((lane >> 4) & 1) * 8]);
                uint32_t bfr[4];
                ldm_x4(bfr, bd);
#pragma unroll
                for (int mb = 0; mb < 2; ++mb) {
                    mma_bf16(acc[mb][2 * qb],     afr[mb], bfr[0], bfr[2]);
                    mma_bf16(acc[mb][2 * qb + 1], afr[mb], bfr[1], bfr[3]);
                }
            }
        }
        if (ch < 15) {
            STS_X(buf ^ 1);
            CP_WAIT0();
        }
        __syncthreads();
    }

    // reduce ||x||^2 across the 8 threads sharing each pixel-oct, compute rn
#pragma unroll
    for (int i = 0; i < 8; ++i)
        sqs[tid >> 4][(tid & 15) * 8 + i] = sq[i];
    __syncthreads();
    {
        float s = 0.f;
#pragma unroll
        for (int j = 0; j < 8; ++j) s += sqs[j][tid];
        rn[tid] = 1.f / fmaxf(sqrtf(s), 1e-12f);
    }
    __syncthreads();

    // softmax over K per pixel, in registers; logits scaled by rn here.
#pragma unroll
    for (int mb = 0; mb < 2; ++mb) {
#pragma unroll
        for (int half = 0; half < 2; ++half) {
            int pl = warp * 32 + mb * 16 + half * 8 + gq;
            int p = p0 + pl;
            float rnv = rn[pl];
            float mx = -1e30f;
#pragma unroll
            for (int nb = 0; nb < 8; ++nb) {
                float l0 = acc[mb][nb][half * 2] * rnv;
                float l1 = acc[mb][nb][half * 2 + 1] * rnv;
                acc[mb][nb][half * 2] = l0;
                acc[mb][nb][half * 2 + 1] = l1;
                mx = fmaxf(mx, fmaxf(l0, l1));
            }
            mx = fmaxf(mx, __shfl_xor_sync(0xffffffff, mx, 1));
            mx = fmaxf(mx, __shfl_xor_sync(0xffffffff, mx, 2));
            float ssum = 0.f;
#pragma unroll
            for (int nb = 0; nb < 8; ++nb) {
                float e0 = __expf(acc[mb][nb][half * 2] - mx);
                float e1 = __expf(acc[mb][nb][half * 2 + 1] - mx);
                acc[mb][nb][half * 2] = e0;
                acc[mb][nb][half * 2 + 1] = e1;
                ssum += e0 + e1;
            }
            ssum += __shfl_xor_sync(0xffffffff, ssum, 1);
            ssum += __shfl_xor_sync(0xffffffff, ssum, 2);
            float inv = (p < PP) ? 1.f / ssum : 0.f;
            __nv_bfloat16* op = g_soft + (size_t)n * KK * PP + p;
#pragma unroll
            for (int nb = 0; nb < 8; ++nb) {
                float a0 = acc[mb][nb][half * 2] * inv;
                float a1 = acc[mb][nb][half * 2 + 1] * inv;
                acc[mb][nb][half * 2] = a0;
                acc[mb][nb][half * 2 + 1] = a1;
                if (p < PP) {
                    op[(size_t)(nb * 8 + 2 * tig) * PP]     = __float2bfloat16_rn(a0 * rnv);
                    op[(size_t)(nb * 8 + 2 * tig + 1) * PP] = __float2bfloat16_rn(a1 * rnv);
                }
            }
        }
    }

    // per-tile a_sum per k (fp32)
    float skE[8], skO[8];
#pragma unroll
    for (int nb = 0; nb < 8; ++nb) {
        skE[nb] = acc[0][nb][0] + acc[0][nb][2] + acc[1][nb][0] + acc[1][nb][2];
        skO[nb] = acc[0][nb][1] + acc[0][nb][3] + acc[1][nb][1] + acc[1][nb][3];
    }
#pragma unroll
    for (int mask = 4; mask <= 16; mask <<= 1)
#pragma unroll
        for (int nb = 0; nb < 8; ++nb) {
            skE[nb] += __shfl_xor_sync(0xffffffff, skE[nb], mask);
            skO[nb] += __shfl_xor_sync(0xffffffff, skO[nb], mask);
        }
    if (lane < 4) {
#pragma unroll
        for (int nb = 0; nb < 8; ++nb) {
            sred[warp][nb * 8 + 2 * lane]     = skE[nb];
            sred[warp][nb * 8 + 2 * lane + 1] = skO[nb];
        }
    }
    __syncthreads();
    if (tid < KK)
        g_asumt[(n * KK + tid) * NTILE + bx] =
            sred[0][tid] + sred[1][tid] + sred[2][tid] + sred[3][tid];
#undef LDG_X
#undef STS_X
#undef CPA_W
}

// ---------------------------------------------------------------------------
// 3) agg GEMM (bf16 mma + ldmatrix): aggp[ps,n,k,d] = sum_p a[k][p] * x[d][p]
//    Warp owns a 32-col d-range (4 n8 blocks), shares the 4 k m-blocks.
//    Per step: 4 A-ldmatrix + 2 B-ldmatrix for 16 MMAs. a_s staged via cp.async.
// ---------------------------------------------------------------------------
__global__ void __launch_bounds__(128) k_agg(const float* __restrict__ x) {
    const int d0 = blockIdx.x * 128;
    const int n  = blockIdx.y;
    const int ps = blockIdx.z;
    const int tid  = threadIdx.x;
    const int warp = tid >> 5;
    const int lane = tid & 31;

    __shared__ __align__(16) uint16_t a_s[2][64 * 40];    // [k][p] pitch 40 (80B)
    __shared__ __align__(16) uint16_t x_s[2][128 * 40];   // [d][p] pitch 40 (80B)

    float acc[4][4][4];
#pragma unroll
    for (int mb = 0; mb < 4; ++mb)
#pragma unroll
        for (int nb = 0; nb < 4; ++nb)
#pragma unroll
            for (int r = 0; r < 4; ++r) acc[mb][nb][r] = 0.f;

    const float* xn = x + (size_t)n * DD * PP;
    const __nv_bfloat16* an = g_soft + (size_t)n * KK * PP;
    const int pbeg = ps * PCHUNK;

    float4 vx[4][2];   // x: 512 tasks (128 rows x 4 octs), 4/thread

#define LDG_XA(pc0)                                                             \
    {                                                                           \
        _Pragma("unroll")                                                       \
        for (int t4 = 0; t4 < 4; ++t4) {                                        \
            int e = t4 * 128 + tid, row = e >> 2, oct = e & 3;                  \
            const float* s = xn + (size_t)(d0 + row) * PP + (pc0) + oct * 8;    \
            vx[t4][0] = *(const float4*)s;                                      \
            vx[t4][1] = *(const float4*)(s + 4);                                \
        }                                                                       \
    }

#define STS_XA(buf)                                                             \
    {                                                                           \
        _Pragma("unroll")                                                       \
        for (int t4 = 0; t4 < 4; ++t4) {                                        \
            int e = t4 * 128 + tid, row = e >> 2, oct = e & 3;                  \
            uint4 o;                                                            \
            o.x = pack_bf2(vx[t4][0].x, vx[t4][0].y);                           \
            o.y = pack_bf2(vx[t4][0].z, vx[t4][0].w);                           \
            o.z = pack_bf2(vx[t4][1].x, vx[t4][1].y);                           \
            o.w = pack_bf2(vx[t4][1].z, vx[t4][1].w);                           \
            *(uint4*)&x_s[buf][row * 40 + oct * 8] = o;                         \
        }                                                                       \
    }

#define CPA_A(pc0, buf)                                                         \
    {                                                                           \
        _Pragma("unroll")                                                       \
        for (int t2 = 0; t2 < 2; ++t2) {                                        \
            int e = t2 * 128 + tid, row = e >> 2, c = e & 3;                    \
            cp_async16((uint32_t)__cvta_generic_to_shared(                      \
                           &a_s[buf][row * 40 + c * 8]),                        \
                       an + (size_t)row * PP + (pc0) + c * 8);                  \
        }                                                                       \
    }

    CPA_A(pbeg, 0);
    CP_COMMIT();
    LDG_XA(pbeg);
    STS_XA(0);
    CP_WAIT0();
    __syncthreads();

    const int NCH = PCHUNK / 32;   // 14
    for (int ch = 0; ch < NCH; ++ch) {
        int buf = ch & 1;
        if (ch < NCH - 1) {
            LDG_XA(pbeg + (ch + 1) * 32);
            CPA_A(pbeg + (ch + 1) * 32, buf ^ 1);
            CP_COMMIT();
        }
#pragma unroll
        for (int s = 0; s < 2; ++s) {
            int rbase = (lane & 7) + ((lane >> 3) & 1) * 8;
            int cofs  = s * 16 + ((lane >> 4) & 1) * 8;
            uint32_t afr[4][4];
#pragma unroll
            for (int mb = 0; mb < 4; ++mb) {
                uint32_t ad = (uint32_t)__cvta_generic_to_shared(
                    &a_s[buf][(mb * 16 + rbase) * 40 + cofs]);
                ldm_x4(afr[mb], ad);
            }
#pragma unroll
            for (int nq = 0; nq < 2; ++nq) {
                uint32_t bd = (uint32_t)__cvta_generic_to_shared(
                    &x_s[buf][(warp * 32 + nq * 16 + rbase) * 40 + cofs]);
                uint32_t bfr[4];
                ldm_x4(bfr, bd);
#pragma unroll
                for (int mb = 0; mb < 4; ++mb) {
                    mma_bf16(acc[mb][2 * nq],     afr[mb], bfr[0], bfr[2]);
                    mma_bf16(acc[mb][2 * nq + 1], afr[mb], bfr[1], bfr[3]);
                }
            }
        }
        if (ch < NCH - 1) {
            STS_XA(buf ^ 1);
            CP_WAIT0();
        }
        __syncthreads();
    }

    // epilogue: k = mb*16 + r (+8), d = d0 + warp*32 + nb*8 + cq
    float* op = g_aggp + ((size_t)(ps * NN + n) * KK) * DD + d0 + warp * 32;
    int r = lane >> 2, cq = (lane & 3) * 2;
#pragma unroll
    for (int mb = 0; mb < 4; ++mb)
#pragma unroll
        for (int nb = 0; nb < 4; ++nb) {
            int d = nb * 8 + cq;
            *(float2*)&op[(size_t)(mb * 16 + r) * DD + d] =
                make_float2(acc[mb][nb][0], acc[mb][nb][1]);
            *(float2*)&op[(size_t)(mb * 16 + r + 8) * DD + d] =
                make_float2(acc[mb][nb][2], acc[mb][nb][3]);
        }
#undef LDG_XA
#undef STS_XA
#undef CPA_A
}

// ---------------------------------------------------------------------------
// 4) vlad: a_sum (tile partials) + (agg - a_sum*c) + intra L2 norm
// ---------------------------------------------------------------------------
__global__ void __launch_bounds__(128) k_vlad(const float* __restrict__ centroids,
                                              float* __restrict__ out) {
    const int k = blockIdx.x;
    const int n = blockIdx.y;
    const int tid = threadIdx.x;
    __shared__ float red[128];

    float asum = 0.f;
    const float* at = g_asumt + (n * KK + k) * NTILE;
#pragma unroll
    for (int t = 0; t < NTILE; ++t) asum += at[t];

    float v[4];
    float ss = 0.f;
#pragma unroll
    for (int j = 0; j < 4; ++j) {
        int d = j * 128 + tid;
        float a = 0.f;
#pragma unroll
        for (int ps = 0; ps < PSPLIT; ++ps)
            a += g_aggp[(((size_t)ps * NN + n) * KK + k) * DD + d];
        v[j] = a - asum * centroids[k * DD + d];
        ss = fmaf(v[j], v[j], ss);
    }
    red[tid] = ss;
    __syncthreads();
    for (int w = 64; w > 0; w >>= 1) {
        if (tid < w) red[tid] += red[tid + w];
        __syncthreads();
    }
    float rinv = 1.f / fmaxf(sqrtf(red[0]), 1e-12f);
    const size_t base = ((size_t)n * KK + k) * DD;
#pragma unroll
    for (int j = 0; j < 4; ++j)
        out[base + j * 128 + tid] = v[j] * rinv;
}

// ---------------------------------------------------------------------------
// 5) global L2 norm per n over K*D
// ---------------------------------------------------------------------------
__global__ void __launch_bounds__(256) k_gnorm(float* __restrict__ out) {
    const int n = blockIdx.x;
    const int tid = threadIdx.x;
    __shared__ float red[256];
    float* row = out + (size_t)n * KK * DD;
    float ss = 0.f;
    for (int i = tid; i < KK * DD; i += 256) {
        float v = row[i];
        ss = fmaf(v, v, ss);
    }
    red[tid] = ss;
    __syncthreads();
    for (int w = 128; w > 0; w >>= 1) {
        if (tid < w) red[tid] += red[tid + w];
        __syncthreads();
    }
    float rinv = 1.f / fmaxf(sqrtf(red[0]), 1e-12f);
    for (int i = tid; i < KK * DD; i += 256) row[i] *= rinv;
}

// ---------------------------------------------------------------------------
extern "C" void kernel_launch(void* const* d_in, const int* in_sizes, int n_in,
                              void* d_out, int out_size) {
    const float* x = (const float*)d_in[0];        // (32, 512, 56, 56)
    const float* w = (const float*)d_in[1];        // (64, 512)
    const float* c = (const float*)d_in[2];        // (64, 512)
    float* out = (float*)d_out;                    // (32, 32768) fp32

    k_wbf<<<(KK * DD / 2 + 255) / 256, 256>>>(w);

    dim3 gB(NTILE, NN);                            // 25 x 32
    k_logits_softmax<<<gB, 128>>>(x);

    dim3 gC(DD / 128, NN, PSPLIT);                 // 4 x 32 x 7 = 896 CTAs
    k_agg<<<gC, 128>>>(x);

    dim3 gD(KK, NN);                               // 64 x 32
    k_vlad<<<gD, 128>>>(c, out);

    k_gnorm<<<NN, 256>>>(out);
}

// round 9
// speedup vs baseline: 5.7796x; 1.0216x over previous
#include <cuda_runtime.h>
#include <cuda_bf16.h>
#include <math.h>
#include <stdint.h>

#define NN 32
#define DD 512
#define PP 3136
#define KK 64
#define PSPLIT 7
#define PCHUNK 448   // PP / PSPLIT = 14 * 32 exactly
#define NTILE 25     // ceil(PP/128)

// Scratch (static device globals — no allocation)
__device__ __align__(16) __nv_bfloat16 g_wbf[KK * DD];               // 64 KB
__device__ __align__(16) __nv_bfloat16 g_soft[(size_t)NN * KK * PP]; // a*rn, 12.8 MB
__device__ float g_aggp[(size_t)PSPLIT * NN * KK * DD];              // 28.7 MB
__device__ float g_asumt[NN * KK * NTILE];                           // 200 KB
__device__ float g_nsq[NN * KK];                                     // per-row ||v̂||²

// ---------------------------------------------------------------------------
__device__ __forceinline__ uint32_t pack_bf2(float lo, float hi) {
    uint32_t r;
    asm("cvt.rn.bf16x2.f32 %0, %1, %2;" : "=r"(r) : "f"(hi), "f"(lo));
    return r;
}
__device__ __forceinline__ void ldm_x4(uint32_t r[4], uint32_t addr) {
    asm volatile("ldmatrix.sync.aligned.m8n8.x4.shared.b16 {%0,%1,%2,%3}, [%4];"
                 : "=r"(r[0]), "=r"(r[1]), "=r"(r[2]), "=r"(r[3]) : "r"(addr));
}
__device__ __forceinline__ void ldm_x4t(uint32_t r[4], uint32_t addr) {
    asm volatile("ldmatrix.sync.aligned.m8n8.x4.trans.shared.b16 {%0,%1,%2,%3}, [%4];"
                 : "=r"(r[0]), "=r"(r[1]), "=r"(r[2]), "=r"(r[3]) : "r"(addr));
}
__device__ __forceinline__ void mma_bf16(float c[4], const uint32_t a[4],
                                         uint32_t b0, uint32_t b1) {
    asm volatile("mma.sync.aligned.m16n8k16.row.col.f32.bf16.bf16.f32 "
                 "{%0,%1,%2,%3}, {%4,%5,%6,%7}, {%8,%9}, {%0,%1,%2,%3};"
                 : "+f"(c[0]), "+f"(c[1]), "+f"(c[2]), "+f"(c[3])
                 : "r"(a[0]), "r"(a[1]), "r"(a[2]), "r"(a[3]), "r"(b0), "r"(b1));
}
__device__ __forceinline__ void cp_async16(uint32_t saddr, const void* g) {
    asm volatile("cp.async.ca.shared.global [%0], [%1], 16;" :: "r"(saddr), "l"(g));
}
#define CP_COMMIT() asm volatile("cp.async.commit_group;")
#define CP_WAIT0()  asm volatile("cp.async.wait_group 0;")

// ---------------------------------------------------------------------------
// 1) convert W to bf16 (row-major [k][d])
// ---------------------------------------------------------------------------
__global__ void __launch_bounds__(256) k_wbf(const float* __restrict__ w) {
    int i = blockIdx.x * 256 + threadIdx.x;
    if (i >= KK * DD / 2) return;
    ((uint32_t*)g_wbf)[i] = pack_bf2(w[2 * i], w[2 * i + 1]);
}

// ---------------------------------------------------------------------------
// 2) fused: per-pixel L2 norm + logits GEMM (bf16 mma) + softmax over K.
//    GEMM on UNNORMALIZED x; logits scaled by rn[p] post-GEMM (rn is a
//    per-pixel scalar so (W·x̂) = (W·x)·rn). ||x||² accumulated during staging.
// ---------------------------------------------------------------------------
__global__ void __launch_bounds__(128) k_logits_softmax(const float* __restrict__ x) {
    const int bx = blockIdx.x;
    const int n  = blockIdx.y;
    const int p0 = bx * 128;
    const int tid  = threadIdx.x;
    const int warp = tid >> 5;
    const int lane = tid & 31;
    const int gq   = lane >> 2;
    const int tig  = lane & 3;

    __shared__ __align__(16) uint16_t x_s[2][32 * 136];   // [d][p] pitch 136 (272B)
    __shared__ __align__(16) uint16_t w_s[2][64 * 40];    // [k][d] pitch 40 (80B)
    __shared__ float rn[128];
    __shared__ float sred[4][64];
    __shared__ float sqs[8][128];

    const int valid = (PP - p0 < 128) ? (PP - p0) : 128;   // 128 or 64

    float acc[2][8][4];
#pragma unroll
    for (int mb = 0; mb < 2; ++mb)
#pragma unroll
        for (int nb = 0; nb < 8; ++nb)
#pragma unroll
            for (int r = 0; r < 4; ++r) acc[mb][nb][r] = 0.f;

    float sq[8];
#pragma unroll
    for (int i = 0; i < 8; ++i) sq[i] = 0.f;

    const float* xn = x + (size_t)n * DD * PP;
    float4 vx[4][2];

#define LDG_X(d0)                                                               \
    {                                                                           \
        _Pragma("unroll")                                                       \
        for (int t4 = 0; t4 < 4; ++t4) {                                        \
            int e = t4 * 128 + tid, row = e >> 4, oct = e & 15;                 \
            if (oct * 8 < valid) {                                              \
                const float* s = xn + (size_t)((d0) + row) * PP + p0 + oct * 8; \
                vx[t4][0] = *(const float4*)s;                                  \
                vx[t4][1] = *(const float4*)(s + 4);                            \
            } else {                                                            \
                vx[t4][0] = make_float4(0.f, 0.f, 0.f, 0.f);                    \
                vx[t4][1] = make_float4(0.f, 0.f, 0.f, 0.f);                    \
            }                                                                   \
        }                                                                       \
    }

#define STS_X(buf)                                                              \
    {                                                                           \
        _Pragma("unroll")                                                       \
        for (int t4 = 0; t4 < 4; ++t4) {                                        \
            int e = t4 * 128 + tid, row = e >> 4, oct = e & 15;                 \
            sq[0] = fmaf(vx[t4][0].x, vx[t4][0].x, sq[0]);                      \
            sq[1] = fmaf(vx[t4][0].y, vx[t4][0].y, sq[1]);                      \
            sq[2] = fmaf(vx[t4][0].z, vx[t4][0].z, sq[2]);                      \
            sq[3] = fmaf(vx[t4][0].w, vx[t4][0].w, sq[3]);                      \
            sq[4] = fmaf(vx[t4][1].x, vx[t4][1].x, sq[4]);                      \
            sq[5] = fmaf(vx[t4][1].y, vx[t4][1].y, sq[5]);                      \
            sq[6] = fmaf(vx[t4][1].z, vx[t4][1].z, sq[6]);                      \
            sq[7] = fmaf(vx[t4][1].w, vx[t4][1].w, sq[7]);                      \
            uint4 o;                                                            \
            o.x = pack_bf2(vx[t4][0].x, vx[t4][0].y);                           \
            o.y = pack_bf2(vx[t4][0].z, vx[t4][0].w);                           \
            o.z = pack_bf2(vx[t4][1].x, vx[t4][1].y);                           \
            o.w = pack_bf2(vx[t4][1].z, vx[t4][1].w);                           \
            *(uint4*)&x_s[buf][row * 136 + oct * 8] = o;                        \
        }                                                                       \
    }

#define CPA_W(d0, buf)                                                          \
    {                                                                           \
        _Pragma("unroll")                                                       \
        for (int t2 = 0; t2 < 2; ++t2) {                                        \
            int e = t2 * 128 + tid, row = e >> 2, c = e & 3;                    \
            cp_async16((uint32_t)__cvta_generic_to_shared(                      \
                           &w_s[buf][row * 40 + c * 8]),                        \
                       g_wbf + row * DD + (d0) + c * 8);                        \
        }                                                                       \
    }

    CPA_W(0, 0);
    CP_COMMIT();
    LDG_X(0);
    STS_X(0);
    CP_WAIT0();
    __syncthreads();

    for (int ch = 0; ch < 16; ++ch) {
        int buf = ch & 1;
        if (ch < 15) {
            LDG_X((ch + 1) * 32);
            CPA_W((ch + 1) * 32, buf ^ 1);
            CP_COMMIT();
        }
#pragma unroll
        for (int s = 0; s < 2; ++s) {
            uint32_t afr[2][4];
#pragma unroll
            for (int mb = 0; mb < 2; ++mb) {
                int row  = s * 16 + (lane & 7) + ((lane >> 4) & 1) * 8;
                int pcol = (warp * 2 + mb) * 16 + ((lane >> 3) & 1) * 8;
                uint32_t ad = (uint32_t)__cvta_generic_to_shared(
                    &x_s[buf][row * 136 + pcol]);
                ldm_x4t(afr[mb], ad);
            }
#pragma unroll
            for (int qb = 0; qb < 4; ++qb) {
                int row = qb * 16 + (lane & 7) + ((lane >> 3) & 1) * 8;
                uint32_t bd = (uint32_t)__cvta_generic_to_shared(
                    &w_s[buf][row * 40 + s * 16 + ((lane >> 4) & 1) * 8]);
                uint32_t bfr[4];
                ldm_x4(bfr, bd);
#pragma unroll
                for (int mb = 0; mb < 2; ++mb) {
                    mma_bf16(acc[mb][2 * qb],     afr[mb], bfr[0], bfr[2]);
                    mma_bf16(acc[mb][2 * qb + 1], afr[mb], bfr[1], bfr[3]);
                }
            }
        }
        if (ch < 15) {
            STS_X(buf ^ 1);
            CP_WAIT0();
        }
        __syncthreads();
    }

    // reduce ||x||² across the 8 threads sharing each pixel-oct, compute rn
#pragma unroll
    for (int i = 0; i < 8; ++i)
        sqs[tid >> 4][(tid & 15) * 8 + i] = sq[i];
    __syncthreads();
    {
        float s = 0.f;
#pragma unroll
        for (int j = 0; j < 8; ++j) s += sqs[j][tid];
        rn[tid] = 1.f / fmaxf(sqrtf(s), 1e-12f);
    }
    __syncthreads();

    // softmax over K per pixel, in registers; logits scaled by rn here.
#pragma unroll
    for (int mb = 0; mb < 2; ++mb) {
#pragma unroll
        for (int half = 0; half < 2; ++half) {
            int pl = warp * 32 + mb * 16 + half * 8 + gq;
            int p = p0 + pl;
            float rnv = rn[pl];
            float mx = -1e30f;
#pragma unroll
            for (int nb = 0; nb < 8; ++nb) {
                float l0 = acc[mb][nb][half * 2] * rnv;
                float l1 = acc[mb][nb][half * 2 + 1] * rnv;
                acc[mb][nb][half * 2] = l0;
                acc[mb][nb][half * 2 + 1] = l1;
                mx = fmaxf(mx, fmaxf(l0, l1));
            }
            mx = fmaxf(mx, __shfl_xor_sync(0xffffffff, mx, 1));
            mx = fmaxf(mx, __shfl_xor_sync(0xffffffff, mx, 2));
            float ssum = 0.f;
#pragma unroll
            for (int nb = 0; nb < 8; ++nb) {
                float e0 = __expf(acc[mb][nb][half * 2] - mx);
                float e1 = __expf(acc[mb][nb][half * 2 + 1] - mx);
                acc[mb][nb][half * 2] = e0;
                acc[mb][nb][half * 2 + 1] = e1;
                ssum += e0 + e1;
            }
            ssum += __shfl_xor_sync(0xffffffff, ssum, 1);
            ssum += __shfl_xor_sync(0xffffffff, ssum, 2);
            float inv = (p < PP) ? 1.f / ssum : 0.f;
            __nv_bfloat16* op = g_soft + (size_t)n * KK * PP + p;
#pragma unroll
            for (int nb = 0; nb < 8; ++nb) {
                float a0 = acc[mb][nb][half * 2] * inv;
                float a1 = acc[mb][nb][half * 2 + 1] * inv;
                acc[mb][nb][half * 2] = a0;
                acc[mb][nb][half * 2 + 1] = a1;
                if (p < PP) {
                    op[(size_t)(nb * 8 + 2 * tig) * PP]     = __float2bfloat16_rn(a0 * rnv);
                    op[(size_t)(nb * 8 + 2 * tig + 1) * PP] = __float2bfloat16_rn(a1 * rnv);
                }
            }
        }
    }

    // per-tile a_sum per k (fp32)
    float skE[8], skO[8];
#pragma unroll
    for (int nb = 0; nb < 8; ++nb) {
        skE[nb] = acc[0][nb][0] + acc[0][nb][2] + acc[1][nb][0] + acc[1][nb][2];
        skO[nb] = acc[0][nb][1] + acc[0][nb][3] + acc[1][nb][1] + acc[1][nb][3];
    }
#pragma unroll
    for (int mask = 4; mask <= 16; mask <<= 1)
#pragma unroll
        for (int nb = 0; nb < 8; ++nb) {
            skE[nb] += __shfl_xor_sync(0xffffffff, skE[nb], mask);
            skO[nb] += __shfl_xor_sync(0xffffffff, skO[nb], mask);
        }
    if (lane < 4) {
#pragma unroll
        for (int nb = 0; nb < 8; ++nb) {
            sred[warp][nb * 8 + 2 * lane]     = skE[nb];
            sred[warp][nb * 8 + 2 * lane + 1] = skO[nb];
        }
    }
    __syncthreads();
    if (tid < KK)
        g_asumt[(n * KK + tid) * NTILE + bx] =
            sred[0][tid] + sred[1][tid] + sred[2][tid] + sred[3][tid];
#undef LDG_X
#undef STS_X
#undef CPA_W
}

// ---------------------------------------------------------------------------
// 3) agg GEMM (bf16 mma + ldmatrix): aggp[ps,n,k,d] = sum_p a[k][p] * x[d][p]
//    Warp owns a 32-col d-range (4 n8 blocks), shares the 4 k m-blocks.
// ---------------------------------------------------------------------------
__global__ void __launch_bounds__(128) k_agg(const float* __restrict__ x) {
    const int d0 = blockIdx.x * 128;
    const int n  = blockIdx.y;
    const int ps = blockIdx.z;
    const int tid  = threadIdx.x;
    const int warp = tid >> 5;
    const int lane = tid & 31;

    __shared__ __align__(16) uint16_t a_s[2][64 * 40];    // [k][p] pitch 40 (80B)
    __shared__ __align__(16) uint16_t x_s[2][128 * 40];   // [d][p] pitch 40 (80B)

    float acc[4][4][4];
#pragma unroll
    for (int mb = 0; mb < 4; ++mb)
#pragma unroll
        for (int nb = 0; nb < 4; ++nb)
#pragma unroll
            for (int r = 0; r < 4; ++r) acc[mb][nb][r] = 0.f;

    const float* xn = x + (size_t)n * DD * PP;
    const __nv_bfloat16* an = g_soft + (size_t)n * KK * PP;
    const int pbeg = ps * PCHUNK;

    float4 vx[4][2];

#define LDG_XA(pc0)                                                             \
    {                                                                           \
        _Pragma("unroll")                                                       \
        for (int t4 = 0; t4 < 4; ++t4) {                                        \
            int e = t4 * 128 + tid, row = e >> 2, oct = e & 3;                  \
            const float* s = xn + (size_t)(d0 + row) * PP + (pc0) + oct * 8;    \
            vx[t4][0] = *(const float4*)s;                                      \
            vx[t4][1] = *(const float4*)(s + 4);                                \
        }                                                                       \
    }

#define STS_XA(buf)                                                             \
    {                                                                           \
        _Pragma("unroll")                                                       \
        for (int t4 = 0; t4 < 4; ++t4) {                                        \
            int e = t4 * 128 + tid, row = e >> 2, oct = e & 3;                  \
            uint4 o;                                                            \
            o.x = pack_bf2(vx[t4][0].x, vx[t4][0].y);                           \
            o.y = pack_bf2(vx[t4][0].z, vx[t4][0].w);                           \
            o.z = pack_bf2(vx[t4][1].x, vx[t4][1].y);                           \
            o.w = pack_bf2(vx[t4][1].z, vx[t4][1].w);                           \
            *(uint4*)&x_s[buf][row * 40 + oct * 8] = o;                         \
        }                                                                       \
    }

#define CPA_A(pc0, buf)                                                         \
    {                                                                           \
        _Pragma("unroll")                                                       \
        for (int t2 = 0; t2 < 2; ++t2) {                                        \
            int e = t2 * 128 + tid, row = e >> 2, c = e & 3;                    \
            cp_async16((uint32_t)__cvta_generic_to_shared(                      \
                           &a_s[buf][row * 40 + c * 8]),                        \
                       an + (size_t)row * PP + (pc0) + c * 8);                  \
        }                                                                       \
    }

    CPA_A(pbeg, 0);
    CP_COMMIT();
    LDG_XA(pbeg);
    STS_XA(0);
    CP_WAIT0();
    __syncthreads();

    const int NCH = PCHUNK / 32;   // 14
    for (int ch = 0; ch < NCH; ++ch) {
        int buf = ch & 1;
        if (ch < NCH - 1) {
            LDG_XA(pbeg + (ch + 1) * 32);
            CPA_A(pbeg + (ch + 1) * 32, buf ^ 1);
            CP_COMMIT();
        }
#pragma unroll
        for (int s = 0; s < 2; ++s) {
            int rbase = (lane & 7) + ((lane >> 3) & 1) * 8;
            int cofs  = s * 16 + ((lane >> 4) & 1) * 8;
            uint32_t afr[4][4];
#pragma unroll
            for (int mb = 0; mb < 4; ++mb) {
                uint32_t ad = (uint32_t)__cvta_generic_to_shared(
                    &a_s[buf][(mb * 16 + rbase) * 40 + cofs]);
                ldm_x4(afr[mb], ad);
            }
#pragma unroll
            for (int nq = 0; nq < 2; ++nq) {
                uint32_t bd = (uint32_t)__cvta_generic_to_shared(
                    &x_s[buf][(warp * 32 + nq * 16 + rbase) * 40 + cofs]);
                uint32_t bfr[4];
                ldm_x4(bfr, bd);
#pragma unroll
                for (int mb = 0; mb < 4; ++mb) {
                    mma_bf16(acc[mb][2 * nq],     afr[mb], bfr[0], bfr[2]);
                    mma_bf16(acc[mb][2 * nq + 1], afr[mb], bfr[1], bfr[3]);
                }
            }
        }
        if (ch < NCH - 1) {
            STS_XA(buf ^ 1);
            CP_WAIT0();
        }
        __syncthreads();
    }

    // epilogue: k = mb*16 + r (+8), d = d0 + warp*32 + nb*8 + cq
    float* op = g_aggp + ((size_t)(ps * NN + n) * KK) * DD + d0 + warp * 32;
    int r = lane >> 2, cq = (lane & 3) * 2;
#pragma unroll
    for (int mb = 0; mb < 4; ++mb)
#pragma unroll
        for (int nb = 0; nb < 4; ++nb) {
            int d = nb * 8 + cq;
            *(float2*)&op[(size_t)(mb * 16 + r) * DD + d] =
                make_float2(acc[mb][nb][0], acc[mb][nb][1]);
            *(float2*)&op[(size_t)(mb * 16 + r + 8) * DD + d] =
                make_float2(acc[mb][nb][2], acc[mb][nb][3]);
        }
#undef LDG_XA
#undef STS_XA
#undef CPA_A
}

// ---------------------------------------------------------------------------
// 4) vlad: a_sum + (agg - a_sum*c) + intra L2 norm; float4 per thread,
//    7 independent partial loads (MLP). Exports ||v̂||² per row to g_nsq.
// ---------------------------------------------------------------------------
__global__ void __launch_bounds__(128) k_vlad(const float* __restrict__ centroids,
                                              float* __restrict__ out) {
    const int k = blockIdx.x;
    const int n = blockIdx.y;
    const int tid = threadIdx.x;
    __shared__ float red[128];

    float asum = 0.f;
    const float* at = g_asumt + (n * KK + k) * NTILE;
#pragma unroll
    for (int t = 0; t < NTILE; ++t) asum += at[t];

    // each thread owns 4 consecutive d (float4); 7 independent partial loads
    float4 a = make_float4(0.f, 0.f, 0.f, 0.f);
#pragma unroll
    for (int ps = 0; ps < PSPLIT; ++ps) {
        float4 t = *(const float4*)(g_aggp +
            (((size_t)ps * NN + n) * KK + k) * DD + tid * 4);
        a.x += t.x; a.y += t.y; a.z += t.z; a.w += t.w;
    }
    float4 c = *(const float4*)(centroids + k * DD + tid * 4);
    float4 v;
    v.x = a.x - asum * c.x;
    v.y = a.y - asum * c.y;
    v.z = a.z - asum * c.z;
    v.w = a.w - asum * c.w;
    float ss = v.x * v.x + v.y * v.y + v.z * v.z + v.w * v.w;

    red[tid] = ss;
    __syncthreads();
    for (int w = 64; w > 0; w >>= 1) {
        if (tid < w) red[tid] += red[tid + w];
        __syncthreads();
    }
    float sst  = red[0];
    float rinv = 1.f / fmaxf(sqrtf(sst), 1e-12f);
    if (tid == 0) g_nsq[n * KK + k] = sst * rinv * rinv;

    float4 o;
    o.x = v.x * rinv; o.y = v.y * rinv; o.z = v.z * rinv; o.w = v.w * rinv;
    *(float4*)(out + ((size_t)n * KK + k) * DD + tid * 4) = o;
}

// ---------------------------------------------------------------------------
// 5) global L2 norm per n (sum from g_nsq; single float4 scaling pass)
// ---------------------------------------------------------------------------
__global__ void __launch_bounds__(256) k_gnorm(float* __restrict__ out) {
    const int n = blockIdx.x;
    const int tid = threadIdx.x;
    __shared__ float red[64];
    __shared__ float rinv_s;
    if (tid < 64) red[tid] = g_nsq[n * KK + tid];
    __syncthreads();
    if (tid < 32) {
        float s = red[tid] + red[tid + 32];
#pragma unroll
        for (int m = 16; m > 0; m >>= 1)
            s += __shfl_xor_sync(0xffffffff, s, m);
        if (tid == 0) rinv_s = 1.f / fmaxf(sqrtf(s), 1e-12f);
    }
    __syncthreads();
    float rinv = rinv_s;
    float4* row = (float4*)(out + (size_t)n * KK * DD);
#pragma unroll 4
    for (int i = tid; i < KK * DD / 4; i += 256) {
        float4 v = row[i];
        v.x *= rinv; v.y *= rinv; v.z *= rinv; v.w *= rinv;
        row[i] = v;
    }
}

// ---------------------------------------------------------------------------
extern "C" void kernel_launch(void* const* d_in, const int* in_sizes, int n_in,
                              void* d_out, int out_size) {
    const float* x = (const float*)d_in[0];        // (32, 512, 56, 56)
    const float* w = (const float*)d_in[1];        // (64, 512)
    const float* c = (const float*)d_in[2];        // (64, 512)
    float* out = (float*)d_out;                    // (32, 32768) fp32

    k_wbf<<<(KK * DD / 2 + 255) / 256, 256>>>(w);

    dim3 gB(NTILE, NN);                            // 25 x 32
    k_logits_softmax<<<gB, 128>>>(x);

    dim3 gC(DD / 128, NN, PSPLIT);                 // 4 x 32 x 7 = 896 CTAs
    k_agg<<<gC, 128>>>(x);

    dim3 gD(KK, NN);                               // 64 x 32
    k_vlad<<<gD, 128>>>(c, out);

    k_gnorm<<<NN, 256>>>(out);
}